// round 6
// baseline (speedup 1.0000x reference)
#include <cuda_runtime.h>
#include <math.h>

#define BB 64
#define MM 512
#define SS 1024
#define EE 128
#define CC 10000
#define MSPLIT 8
#define NSPLIT 32
#define KCHUNK (SS / NSPLIT)  /* 32 */
#define PREF 8
#define TILES5 313            /* ceil(10000/32) 32-col tiles */
#define GRID5 296             /* 2 persistent blocks per SM */

// ---------------- scratch (device globals; no allocation) ----------------
__device__ __align__(16) float g_partial[BB * MSPLIT * SS];   // 2 MB
__device__ __align__(16) float g_gpart[2 * NSPLIT * BB * EE]; // 2 MB
__device__ __align__(16) float g_u[BB * EE];                  // 32 KB
__device__ __align__(16) float g_logits[BB * CC];             // 2.56 MB (exp(logits))
__device__ __align__(16) float g_psum[BB * TILES5];
__device__ __align__(16) float g_dummy[128 * 256];
__device__ int g_tile_cnt;

// ---------------- kernel 1: reduce stories over M + prefetch weights ------------
__global__ void k1_reduce_stories(const float* __restrict__ stories,
                                  const float* __restrict__ queries,
                                  const float* __restrict__ W1,
                                  const float* __restrict__ W2,
                                  const float* __restrict__ W3) {
    int blk = blockIdx.x;
    int t = threadIdx.x;

    if (blk >= BB * MSPLIT) {  // ---- L2 prefetch blocks ----
        int lane = (blk - BB * MSPLIT) * 256 + t;
        float s = 0.f;
        const float4* a = (const float4*)W1;
        for (int i = lane; i < 32768; i += PREF * 256) {
            float4 v = __ldcg(&a[i]); s += v.x + v.y + v.z + v.w;
        }
        a = (const float4*)W2;
        for (int i = lane; i < 32768; i += PREF * 256) {
            float4 v = __ldcg(&a[i]); s += v.x + v.y + v.z + v.w;
        }
        a = (const float4*)queries;
        for (int i = lane; i < 16384; i += PREF * 256) {
            float4 v = __ldcg(&a[i]); s += v.x + v.y + v.z + v.w;
        }
        a = (const float4*)W3;
        for (int i = lane; i < 4096; i += PREF * 256) {
            float4 v = __ldcg(&a[i]); s += v.x + v.y + v.z + v.w;
        }
        g_dummy[lane] = s;
        return;
    }

    int b = blk / MSPLIT, ms = blk % MSPLIT;
    const float4* src =
        (const float4*)(stories + (size_t)(b * MM + ms * (MM / MSPLIT)) * SS);
    float4 a0 = make_float4(0.f, 0.f, 0.f, 0.f);
    float4 a1 = a0, a2 = a0, a3 = a0;
#pragma unroll 4
    for (int m = 0; m < MM / MSPLIT; m += 4) {
        float4 v0 = __ldcs(&src[(size_t)(m + 0) * (SS / 4) + t]);
        float4 v1 = __ldcs(&src[(size_t)(m + 1) * (SS / 4) + t]);
        float4 v2 = __ldcs(&src[(size_t)(m + 2) * (SS / 4) + t]);
        float4 v3 = __ldcs(&src[(size_t)(m + 3) * (SS / 4) + t]);
        a0.x += v0.x; a0.y += v0.y; a0.z += v0.z; a0.w += v0.w;
        a1.x += v1.x; a1.y += v1.y; a1.z += v1.z; a1.w += v1.w;
        a2.x += v2.x; a2.y += v2.y; a2.z += v2.z; a2.w += v2.w;
        a3.x += v3.x; a3.y += v3.y; a3.z += v3.z; a3.w += v3.w;
    }
    float4 r;
    r.x = (a0.x + a1.x) + (a2.x + a3.x);
    r.y = (a0.y + a1.y) + (a2.y + a3.y);
    r.z = (a0.z + a1.z) + (a2.z + a3.z);
    r.w = (a0.w + a1.w) + (a2.w + a3.w);
    ((float4*)g_partial)[(size_t)blk * (SS / 4) + t] = r;
}

// ---------------- kernel 3: u0 = queries@W1^T, o = ssum@W2^T (split-K x32) ------
__global__ void k3_gemm64(const float* __restrict__ queries,
                          const float* __restrict__ W1,
                          const float* __restrict__ W2,
                          const float* __restrict__ W4) {
    int ks = blockIdx.x;
    int eh = blockIdx.y;
    int which = blockIdx.z;
    const float* W = which ? W2 : W1;
    int kbase = ks * KCHUNK;

    // W4 L2 prefetch for k5 across 128 blocks
    int bid = ks + NSPLIT * eh + NSPLIT * 2 * which;  // 0..127
    int plane = bid * 256 + threadIdx.x;
    float ps = 0.f;
    const float4* w4 = (const float4*)W4;
    for (int i = plane; i < 320000; i += 128 * 256) {
        float4 v = __ldcg(&w4[i]); ps += v.x + v.y + v.z + v.w;
    }

    __shared__ __align__(16) float Xs[32][68];
    __shared__ __align__(16) float Ws[32][68];

    int tid = threadIdx.x;
    int tb = tid & 15, te = tid >> 4;
    int lrow = tid >> 3, lkq = tid & 7;

    float acc[16];
#pragma unroll
    for (int i = 0; i < 16; i++) acc[i] = 0.f;

    {
#pragma unroll
        for (int h = 0; h < 2; h++) {
            int row = lrow + 32 * h;
            float4 xv;
            if (which == 0) {
                xv = *(const float4*)&queries[(size_t)row * SS + kbase + lkq * 4];
            } else {
                xv = make_float4(0.f, 0.f, 0.f, 0.f);
#pragma unroll
                for (int msp = 0; msp < MSPLIT; msp++) {
                    float4 v = *(const float4*)&g_partial[
                        (size_t)(row * MSPLIT + msp) * SS + kbase + lkq * 4];
                    xv.x += v.x; xv.y += v.y; xv.z += v.z; xv.w += v.w;
                }
            }
            float4 wv = *(const float4*)&W[(size_t)(eh * 64 + row) * SS + kbase + lkq * 4];
            Xs[lkq * 4 + 0][row] = xv.x; Xs[lkq * 4 + 1][row] = xv.y;
            Xs[lkq * 4 + 2][row] = xv.z; Xs[lkq * 4 + 3][row] = xv.w;
            Ws[lkq * 4 + 0][row] = wv.x; Ws[lkq * 4 + 1][row] = wv.y;
            Ws[lkq * 4 + 2][row] = wv.z; Ws[lkq * 4 + 3][row] = wv.w;
        }
        __syncthreads();
#pragma unroll
        for (int k = 0; k < 32; k++) {
            float4 xv = *(const float4*)&Xs[k][tb * 4];
            float4 wv = *(const float4*)&Ws[k][te * 4];
            acc[0]  += xv.x * wv.x; acc[1]  += xv.x * wv.y;
            acc[2]  += xv.x * wv.z; acc[3]  += xv.x * wv.w;
            acc[4]  += xv.y * wv.x; acc[5]  += xv.y * wv.y;
            acc[6]  += xv.y * wv.z; acc[7]  += xv.y * wv.w;
            acc[8]  += xv.z * wv.x; acc[9]  += xv.z * wv.y;
            acc[10] += xv.z * wv.z; acc[11] += xv.z * wv.w;
            acc[12] += xv.w * wv.x; acc[13] += xv.w * wv.y;
            acc[14] += xv.w * wv.z; acc[15] += xv.w * wv.w;
        }
    }
#pragma unroll
    for (int i = 0; i < 4; i++)
#pragma unroll
        for (int j = 0; j < 4; j++)
            g_gpart[(size_t)((which * NSPLIT + ks) * BB + tb * 4 + i) * EE +
                    eh * 64 + te * 4 + j] = acc[i * 4 + j];
    g_dummy[plane] = ps;
}

// ---------------- kernel 4: split-K combine + 3 hops + L2 normalize -------------
// Also resets the k5 tile counter (runs strictly before k5 in-stream).
__global__ void k4_hops(const float* __restrict__ W3) {
    __shared__ float us[EE];
    __shared__ float red[4];
    int b = blockIdx.x;
    int f = threadIdx.x;
    if (b == 0 && f == 0) g_tile_cnt = 0;

    float4 w[32];
    const float4* wrow = (const float4*)(W3 + (size_t)f * EE);
#pragma unroll
    for (int q = 0; q < 32; q++) w[q] = __ldcg(&wrow[q]);

    float u = 0.f, o = 0.f;
#pragma unroll
    for (int ks = 0; ks < NSPLIT; ks++) {
        u += g_gpart[(size_t)(ks * BB + b) * EE + f];
        o += g_gpart[(size_t)((NSPLIT + ks) * BB + b) * EE + f];
    }
    us[f] = u;
    __syncthreads();

    float vout = 0.f;
    const float4* us4 = (const float4*)us;
    for (int hop = 0; hop < 3; hop++) {
        float v0 = 0.f, v1 = 0.f, v2 = 0.f, v3 = 0.f;
#pragma unroll
        for (int q = 0; q < 32; q++) {
            float4 uu = us4[q];
            v0 += w[q].x * uu.x;
            v1 += w[q].y * uu.y;
            v2 += w[q].z * uu.z;
            v3 += w[q].w * uu.w;
        }
        float v = o + ((v0 + v1) + (v2 + v3));
        float s = v * v;
#pragma unroll
        for (int off = 16; off; off >>= 1)
            s += __shfl_xor_sync(0xffffffffu, s, off);
        if ((f & 31) == 0) red[f >> 5] = s;
        __syncthreads();
        float tot = (red[0] + red[1]) + (red[2] + red[3]);
        float nrm = fmaxf(sqrtf(tot), 1e-12f);
        vout = v / nrm;
        us[f] = vout;
        __syncthreads();
    }
    g_u[(size_t)b * EE + f] = vout;
}

// ---------------- kernel 5: persistent exp(u @ W4^T), atomic tile queue ---------
// 296 blocks x 256 threads, 2 blocks/SM. 313 tiles of [64b x 32c], K=128.
// Xs ([k][b], 64x128 of g_u) loaded ONCE per block; Ws per tile. Thread tile
// 4b x 2c, software-pipelined, Xs read = 2 wavefronts, Ws read = broadcast.
#define XPAD 68
#define WPAD 36
#define KROWS 132
__global__ void __launch_bounds__(256, 2) k5_logits(const float* __restrict__ W4) {
    extern __shared__ float sm[];
    float* Xs = sm;                        // [KROWS][XPAD]
    float* Ws = sm + KROWS * XPAD;         // [KROWS][WPAD]
    float* rpart = sm + KROWS * (XPAD + WPAD); // [16][65]
    __shared__ int s_tile;

    int tid = threadIdx.x;

    // ---- load Xs once: transpose g_u into [k][b] ----
    {
        int r = tid & 63;        // b
        int qb = tid >> 6;       // 0..3
        const float4* usrc = (const float4*)(g_u + (size_t)r * EE);
#pragma unroll
        for (int j = 0; j < 8; j++) {
            int q = qb + 4 * j;  // k-quad 0..31
            float4 xv = usrc[q];
            Xs[(4 * q + 0) * XPAD + r] = xv.x;
            Xs[(4 * q + 1) * XPAD + r] = xv.y;
            Xs[(4 * q + 2) * XPAD + r] = xv.z;
            Xs[(4 * q + 3) * XPAD + r] = xv.w;
        }
    }

    int tb = tid & 15;   // b-quad: rows tb*4..+3
    int tc = tid >> 4;   // col pair: cols tc*2, tc*2+1
    const float* xbase = Xs + tb * 4;
    const float* wbase = Ws + tc * 2;

    for (;;) {
        if (tid == 0) s_tile = atomicAdd(&g_tile_cnt, 1);
        __syncthreads();  // s_tile visible; prev compute done (Ws safe to overwrite)
        int tile = s_tile;
        if (tile >= TILES5) break;
        int c0 = tile * 32;

        // ---- load Ws tile: [k][c] for 32 cols ----
        {
            int c = tid & 31;
            int h = tid >> 5;   // 0..7
            int crow = c0 + c;
            const float4* wsrc = (const float4*)(W4 + (size_t)crow * EE);
            bool valid = crow < CC;
#pragma unroll
            for (int j = 0; j < 4; j++) {
                int q = h + 8 * j;  // k-quad 0..31
                float4 wv = make_float4(0.f, 0.f, 0.f, 0.f);
                if (valid) wv = wsrc[q];
                Ws[(4 * q + 0) * WPAD + c] = wv.x;
                Ws[(4 * q + 1) * WPAD + c] = wv.y;
                Ws[(4 * q + 2) * WPAD + c] = wv.z;
                Ws[(4 * q + 3) * WPAD + c] = wv.w;
            }
        }
        __syncthreads();

        // ---- compute: pipelined, barrier-free ----
        float a00 = 0.f, a01 = 0.f, a10 = 0.f, a11 = 0.f;
        float a20 = 0.f, a21 = 0.f, a30 = 0.f, a31 = 0.f;
        float4 xa = *(const float4*)(xbase);
        float2 wa = *(const float2*)(wbase);
        float4 xb = *(const float4*)(xbase + XPAD);
        float2 wb = *(const float2*)(wbase + WPAD);
#pragma unroll 8
        for (int k = 0; k < EE; k += 2) {
            float4 xc = *(const float4*)(xbase + (size_t)(k + 2) * XPAD);
            float2 wc = *(const float2*)(wbase + (size_t)(k + 2) * WPAD);
            a00 += xa.x * wa.x; a01 += xa.x * wa.y;
            a10 += xa.y * wa.x; a11 += xa.y * wa.y;
            a20 += xa.z * wa.x; a21 += xa.z * wa.y;
            a30 += xa.w * wa.x; a31 += xa.w * wa.y;
            float4 xd = *(const float4*)(xbase + (size_t)(k + 3) * XPAD);
            float2 wd = *(const float2*)(wbase + (size_t)(k + 3) * WPAD);
            a00 += xb.x * wb.x; a01 += xb.x * wb.y;
            a10 += xb.y * wb.x; a11 += xb.y * wb.y;
            a20 += xb.z * wb.x; a21 += xb.z * wb.y;
            a30 += xb.w * wb.x; a31 += xb.w * wb.y;
            xa = xc; wa = wc;
            xb = xd; wb = wd;
        }

        // ---- epilogue: exp, store, per-tile row partials ----
        int cA = c0 + tc * 2, cB = cA + 1;
        bool vA = cA < CC, vB = cB < CC;
        float e00 = vA ? __expf(a00) : 0.f, e01 = vB ? __expf(a01) : 0.f;
        float e10 = vA ? __expf(a10) : 0.f, e11 = vB ? __expf(a11) : 0.f;
        float e20 = vA ? __expf(a20) : 0.f, e21 = vB ? __expf(a21) : 0.f;
        float e30 = vA ? __expf(a30) : 0.f, e31 = vB ? __expf(a31) : 0.f;
        int b0 = tb * 4;
        if (vA) {
            g_logits[(size_t)(b0 + 0) * CC + cA] = e00;
            g_logits[(size_t)(b0 + 1) * CC + cA] = e10;
            g_logits[(size_t)(b0 + 2) * CC + cA] = e20;
            g_logits[(size_t)(b0 + 3) * CC + cA] = e30;
        }
        if (vB) {
            g_logits[(size_t)(b0 + 0) * CC + cB] = e01;
            g_logits[(size_t)(b0 + 1) * CC + cB] = e11;
            g_logits[(size_t)(b0 + 2) * CC + cB] = e21;
            g_logits[(size_t)(b0 + 3) * CC + cB] = e31;
        }
        rpart[tc * 65 + b0 + 0] = e00 + e01;
        rpart[tc * 65 + b0 + 1] = e10 + e11;
        rpart[tc * 65 + b0 + 2] = e20 + e21;
        rpart[tc * 65 + b0 + 3] = e30 + e31;
        __syncthreads();
        if (tid < BB) {
            float s = 0.f;
#pragma unroll
            for (int t2 = 0; t2 < 16; t2++) s += rpart[t2 * 65 + tid];
            g_psum[(size_t)tid * TILES5 + tile] = s;
        }
    }
}

// ---------------- kernel 6: scale exp by 1/rowsum ----------------
__global__ void k6_scale(float* __restrict__ out) {
    int b = blockIdx.x, ch = blockIdx.y, t = threadIdx.x;
    __shared__ float sred[8];
    float p = g_psum[(size_t)b * TILES5 + t];        // t < 256 < TILES5
    if (t + 256 < TILES5) p += g_psum[(size_t)b * TILES5 + t + 256];
#pragma unroll
    for (int off = 16; off; off >>= 1)
        p += __shfl_xor_sync(0xffffffffu, p, off);
    if ((t & 31) == 0) sred[t >> 5] = p;
    __syncthreads();
    float tot = ((sred[0] + sred[1]) + (sred[2] + sred[3])) +
                ((sred[4] + sred[5]) + (sred[6] + sred[7]));
    float inv = 1.0f / tot;

    int i = ch * 250 + t;
    if (t < 250) {
        float4 v = ((const float4*)(g_logits + (size_t)b * CC))[i];
        float4 r;
        r.x = v.x * inv; r.y = v.y * inv; r.z = v.z * inv; r.w = v.w * inv;
        ((float4*)(out + (size_t)b * CC))[i] = r;
    }
}

// ---------------- launch ----------------
extern "C" void kernel_launch(void* const* d_in, const int* in_sizes, int n_in,
                              void* d_out, int out_size) {
    const float* stories = (const float*)d_in[0];
    const float* queries = (const float*)d_in[1];
    const float* W1 = (const float*)d_in[2];
    const float* W2 = (const float*)d_in[3];
    const float* W3 = (const float*)d_in[4];
    const float* W4 = (const float*)d_in[5];
    float* out = (float*)d_out;

    static int k5_smem = 0;
    int smem5 = (KROWS * (XPAD + WPAD) + 16 * 65) * 4;  // ~59 KB
    if (!k5_smem) {
        cudaFuncSetAttribute(k5_logits,
                             cudaFuncAttributeMaxDynamicSharedMemorySize, smem5);
        k5_smem = 1;
    }

    k1_reduce_stories<<<BB * MSPLIT + PREF, 256>>>(stories, queries, W1, W2, W3);
    dim3 g3(NSPLIT, 2, 2);
    k3_gemm64<<<g3, 256>>>(queries, W1, W2, W4);
    k4_hops<<<BB, EE>>>(W3);
    k5_logits<<<GRID5, 256, smem5>>>(W4);
    dim3 g6(BB, 10);
    k6_scale<<<g6, 256>>>(out);
}

// round 7
// speedup vs baseline: 1.0385x; 1.0385x over previous
#include <cuda_runtime.h>
#include <math.h>

#define BB 64
#define MM 512
#define SS 1024
#define EE 128
#define CC 10000
#define MSPLIT 8
#define NSPLIT 32
#define KCHUNK (SS / NSPLIT)  /* 32 */
#define PREF 8
#define TILES5 313            /* ceil(10000/32) 32-col tiles, one block each */

// ---------------- scratch (device globals; no allocation) ----------------
__device__ __align__(16) float g_partial[BB * MSPLIT * SS];   // 2 MB
__device__ __align__(16) float g_gpart[2 * NSPLIT * BB * EE]; // 2 MB
__device__ __align__(16) float g_u[BB * EE];                  // 32 KB
__device__ __align__(16) float g_logits[BB * CC];             // 2.56 MB (exp(logits))
__device__ __align__(16) float g_psum[BB * TILES5];
__device__ __align__(16) float g_dummy[128 * 256];

// ---------------- kernel 1: reduce stories over M + prefetch weights ------------
__global__ void k1_reduce_stories(const float* __restrict__ stories,
                                  const float* __restrict__ queries,
                                  const float* __restrict__ W1,
                                  const float* __restrict__ W2,
                                  const float* __restrict__ W3) {
    int blk = blockIdx.x;
    int t = threadIdx.x;

    if (blk >= BB * MSPLIT) {  // ---- L2 prefetch blocks ----
        int lane = (blk - BB * MSPLIT) * 256 + t;
        float s = 0.f;
        const float4* a = (const float4*)W1;
        for (int i = lane; i < 32768; i += PREF * 256) {
            float4 v = __ldcg(&a[i]); s += v.x + v.y + v.z + v.w;
        }
        a = (const float4*)W2;
        for (int i = lane; i < 32768; i += PREF * 256) {
            float4 v = __ldcg(&a[i]); s += v.x + v.y + v.z + v.w;
        }
        a = (const float4*)queries;
        for (int i = lane; i < 16384; i += PREF * 256) {
            float4 v = __ldcg(&a[i]); s += v.x + v.y + v.z + v.w;
        }
        a = (const float4*)W3;
        for (int i = lane; i < 4096; i += PREF * 256) {
            float4 v = __ldcg(&a[i]); s += v.x + v.y + v.z + v.w;
        }
        g_dummy[lane] = s;
        return;
    }

    int b = blk / MSPLIT, ms = blk % MSPLIT;
    const float4* src =
        (const float4*)(stories + (size_t)(b * MM + ms * (MM / MSPLIT)) * SS);
    float4 a0 = make_float4(0.f, 0.f, 0.f, 0.f);
    float4 a1 = a0, a2 = a0, a3 = a0;
#pragma unroll 4
    for (int m = 0; m < MM / MSPLIT; m += 4) {
        float4 v0 = __ldcs(&src[(size_t)(m + 0) * (SS / 4) + t]);
        float4 v1 = __ldcs(&src[(size_t)(m + 1) * (SS / 4) + t]);
        float4 v2 = __ldcs(&src[(size_t)(m + 2) * (SS / 4) + t]);
        float4 v3 = __ldcs(&src[(size_t)(m + 3) * (SS / 4) + t]);
        a0.x += v0.x; a0.y += v0.y; a0.z += v0.z; a0.w += v0.w;
        a1.x += v1.x; a1.y += v1.y; a1.z += v1.z; a1.w += v1.w;
        a2.x += v2.x; a2.y += v2.y; a2.z += v2.z; a2.w += v2.w;
        a3.x += v3.x; a3.y += v3.y; a3.z += v3.z; a3.w += v3.w;
    }
    float4 r;
    r.x = (a0.x + a1.x) + (a2.x + a3.x);
    r.y = (a0.y + a1.y) + (a2.y + a3.y);
    r.z = (a0.z + a1.z) + (a2.z + a3.z);
    r.w = (a0.w + a1.w) + (a2.w + a3.w);
    ((float4*)g_partial)[(size_t)blk * (SS / 4) + t] = r;
}

// ---------------- kernel 3: u0 = queries@W1^T, o = ssum@W2^T (split-K x32) ------
__global__ void k3_gemm64(const float* __restrict__ queries,
                          const float* __restrict__ W1,
                          const float* __restrict__ W2,
                          const float* __restrict__ W4) {
    int ks = blockIdx.x;
    int eh = blockIdx.y;
    int which = blockIdx.z;
    const float* W = which ? W2 : W1;
    int kbase = ks * KCHUNK;

    // W4 L2 prefetch for k5 across 128 blocks
    int bid = ks + NSPLIT * eh + NSPLIT * 2 * which;  // 0..127
    int plane = bid * 256 + threadIdx.x;
    float ps = 0.f;
    const float4* w4 = (const float4*)W4;
    for (int i = plane; i < 320000; i += 128 * 256) {
        float4 v = __ldcg(&w4[i]); ps += v.x + v.y + v.z + v.w;
    }

    __shared__ __align__(16) float Xs[32][68];
    __shared__ __align__(16) float Ws[32][68];

    int tid = threadIdx.x;
    int tb = tid & 15, te = tid >> 4;
    int lrow = tid >> 3, lkq = tid & 7;

    float acc[16];
#pragma unroll
    for (int i = 0; i < 16; i++) acc[i] = 0.f;

    {
#pragma unroll
        for (int h = 0; h < 2; h++) {
            int row = lrow + 32 * h;
            float4 xv;
            if (which == 0) {
                xv = *(const float4*)&queries[(size_t)row * SS + kbase + lkq * 4];
            } else {
                xv = make_float4(0.f, 0.f, 0.f, 0.f);
#pragma unroll
                for (int msp = 0; msp < MSPLIT; msp++) {
                    float4 v = *(const float4*)&g_partial[
                        (size_t)(row * MSPLIT + msp) * SS + kbase + lkq * 4];
                    xv.x += v.x; xv.y += v.y; xv.z += v.z; xv.w += v.w;
                }
            }
            float4 wv = *(const float4*)&W[(size_t)(eh * 64 + row) * SS + kbase + lkq * 4];
            Xs[lkq * 4 + 0][row] = xv.x; Xs[lkq * 4 + 1][row] = xv.y;
            Xs[lkq * 4 + 2][row] = xv.z; Xs[lkq * 4 + 3][row] = xv.w;
            Ws[lkq * 4 + 0][row] = wv.x; Ws[lkq * 4 + 1][row] = wv.y;
            Ws[lkq * 4 + 2][row] = wv.z; Ws[lkq * 4 + 3][row] = wv.w;
        }
        __syncthreads();
#pragma unroll
        for (int k = 0; k < 32; k++) {
            float4 xv = *(const float4*)&Xs[k][tb * 4];
            float4 wv = *(const float4*)&Ws[k][te * 4];
            acc[0]  += xv.x * wv.x; acc[1]  += xv.x * wv.y;
            acc[2]  += xv.x * wv.z; acc[3]  += xv.x * wv.w;
            acc[4]  += xv.y * wv.x; acc[5]  += xv.y * wv.y;
            acc[6]  += xv.y * wv.z; acc[7]  += xv.y * wv.w;
            acc[8]  += xv.z * wv.x; acc[9]  += xv.z * wv.y;
            acc[10] += xv.z * wv.z; acc[11] += xv.z * wv.w;
            acc[12] += xv.w * wv.x; acc[13] += xv.w * wv.y;
            acc[14] += xv.w * wv.z; acc[15] += xv.w * wv.w;
        }
    }
#pragma unroll
    for (int i = 0; i < 4; i++)
#pragma unroll
        for (int j = 0; j < 4; j++)
            g_gpart[(size_t)((which * NSPLIT + ks) * BB + tb * 4 + i) * EE +
                    eh * 64 + te * 4 + j] = acc[i * 4 + j];
    g_dummy[plane] = ps;
}

// ---------------- kernel 4: split-K combine + 3 hops + L2 normalize -------------
__global__ void k4_hops(const float* __restrict__ W3) {
    __shared__ float us[EE];
    __shared__ float red[4];
    int b = blockIdx.x;
    int f = threadIdx.x;

    float4 w[32];
    const float4* wrow = (const float4*)(W3 + (size_t)f * EE);
#pragma unroll
    for (int q = 0; q < 32; q++) w[q] = __ldcg(&wrow[q]);

    float u = 0.f, o = 0.f;
#pragma unroll
    for (int ks = 0; ks < NSPLIT; ks++) {
        u += g_gpart[(size_t)(ks * BB + b) * EE + f];
        o += g_gpart[(size_t)((NSPLIT + ks) * BB + b) * EE + f];
    }
    us[f] = u;
    __syncthreads();

    float vout = 0.f;
    const float4* us4 = (const float4*)us;
    for (int hop = 0; hop < 3; hop++) {
        float v0 = 0.f, v1 = 0.f, v2 = 0.f, v3 = 0.f;
#pragma unroll
        for (int q = 0; q < 32; q++) {
            float4 uu = us4[q];
            v0 += w[q].x * uu.x;
            v1 += w[q].y * uu.y;
            v2 += w[q].z * uu.z;
            v3 += w[q].w * uu.w;
        }
        float v = o + ((v0 + v1) + (v2 + v3));
        float s = v * v;
#pragma unroll
        for (int off = 16; off; off >>= 1)
            s += __shfl_xor_sync(0xffffffffu, s, off);
        if ((f & 31) == 0) red[f >> 5] = s;
        __syncthreads();
        float tot = (red[0] + red[1]) + (red[2] + red[3]);
        float nrm = fmaxf(sqrtf(tot), 1e-12f);
        vout = v / nrm;
        us[f] = vout;
        __syncthreads();
    }
    g_u[(size_t)b * EE + f] = vout;
}

// ---------------- kernel 5: exp(u @ W4^T), lane = column mapping ----------------
// grid = 313 (one 64b x 32c tile per block, K=128), block = 256, 3 blocks/SM
// resident -> whole grid is ONE wave, no tail. Thread tile 4b x 2c with
// tc = tid&15 (cols), tb = tid>>4 (rows):
//   Xs float4 read  -> warp BROADCAST (1 wavefront)
//   Ws float2 read  -> 1 wavefront
//   g_logits stores -> coalesced float2 (2 rows/warp/instr, 8 sectors)
#define XPAD 68
#define WPAD 36
#define KROWS 132
__global__ void __launch_bounds__(256, 3) k5_logits(const float* __restrict__ W4) {
    __shared__ __align__(16) float Xs[KROWS * XPAD];
    __shared__ __align__(16) float Ws[KROWS * WPAD];
    __shared__ float rpart[16 * 65];

    int tid = threadIdx.x;
    int c0 = blockIdx.x * 32;

    // ---- load Xs: transpose g_u [b][k] -> [k][b] ----
    {
        int r = tid & 63;        // b
        int qb = tid >> 6;       // 0..3
        const float4* usrc = (const float4*)(g_u + (size_t)r * EE);
#pragma unroll
        for (int j = 0; j < 8; j++) {
            int q = qb + 4 * j;  // k-quad 0..31
            float4 xv = usrc[q];
            Xs[(4 * q + 0) * XPAD + r] = xv.x;
            Xs[(4 * q + 1) * XPAD + r] = xv.y;
            Xs[(4 * q + 2) * XPAD + r] = xv.z;
            Xs[(4 * q + 3) * XPAD + r] = xv.w;
        }
    }
    // ---- load Ws: W4 tile [c][k] -> [k][c], 32 cols ----
    {
        int c = tid & 31;
        int h = tid >> 5;   // 0..7
        int crow = c0 + c;
        const float4* wsrc = (const float4*)(W4 + (size_t)crow * EE);
        bool valid = crow < CC;
#pragma unroll
        for (int j = 0; j < 4; j++) {
            int q = h + 8 * j;  // k-quad 0..31
            float4 wv = make_float4(0.f, 0.f, 0.f, 0.f);
            if (valid) wv = wsrc[q];
            Ws[(4 * q + 0) * WPAD + c] = wv.x;
            Ws[(4 * q + 1) * WPAD + c] = wv.y;
            Ws[(4 * q + 2) * WPAD + c] = wv.z;
            Ws[(4 * q + 3) * WPAD + c] = wv.w;
        }
    }
    __syncthreads();

    int tc = tid & 15;   // col pair: cols tc*2, tc*2+1
    int tb = tid >> 4;   // b-quad: rows tb*4..+3
    const float* xbase = Xs + tb * 4;
    const float* wbase = Ws + tc * 2;

    // ---- compute: pipelined, barrier-free, 2 wavefronts per k per warp ----
    float a00 = 0.f, a01 = 0.f, a10 = 0.f, a11 = 0.f;
    float a20 = 0.f, a21 = 0.f, a30 = 0.f, a31 = 0.f;
    float4 xa = *(const float4*)(xbase);
    float2 wa = *(const float2*)(wbase);
    float4 xb = *(const float4*)(xbase + XPAD);
    float2 wb = *(const float2*)(wbase + WPAD);
#pragma unroll 8
    for (int k = 0; k < EE; k += 2) {
        float4 xc = *(const float4*)(xbase + (size_t)(k + 2) * XPAD);
        float2 wc = *(const float2*)(wbase + (size_t)(k + 2) * WPAD);
        a00 += xa.x * wa.x; a01 += xa.x * wa.y;
        a10 += xa.y * wa.x; a11 += xa.y * wa.y;
        a20 += xa.z * wa.x; a21 += xa.z * wa.y;
        a30 += xa.w * wa.x; a31 += xa.w * wa.y;
        float4 xd = *(const float4*)(xbase + (size_t)(k + 3) * XPAD);
        float2 wd = *(const float2*)(wbase + (size_t)(k + 3) * WPAD);
        a00 += xb.x * wb.x; a01 += xb.x * wb.y;
        a10 += xb.y * wb.x; a11 += xb.y * wb.y;
        a20 += xb.z * wb.x; a21 += xb.z * wb.y;
        a30 += xb.w * wb.x; a31 += xb.w * wb.y;
        xa = xc; wa = wc;
        xb = xd; wb = wd;
    }

    // ---- epilogue: exp, coalesced float2 stores, per-tile row partials ----
    int cA = c0 + tc * 2;
    bool valid = cA < CC;  // CC even => pair fully valid or fully invalid
    float e00 = valid ? __expf(a00) : 0.f, e01 = valid ? __expf(a01) : 0.f;
    float e10 = valid ? __expf(a10) : 0.f, e11 = valid ? __expf(a11) : 0.f;
    float e20 = valid ? __expf(a20) : 0.f, e21 = valid ? __expf(a21) : 0.f;
    float e30 = valid ? __expf(a30) : 0.f, e31 = valid ? __expf(a31) : 0.f;
    int b0 = tb * 4;
    if (valid) {
        *(float2*)&g_logits[(size_t)(b0 + 0) * CC + cA] = make_float2(e00, e01);
        *(float2*)&g_logits[(size_t)(b0 + 1) * CC + cA] = make_float2(e10, e11);
        *(float2*)&g_logits[(size_t)(b0 + 2) * CC + cA] = make_float2(e20, e21);
        *(float2*)&g_logits[(size_t)(b0 + 3) * CC + cA] = make_float2(e30, e31);
    }
    rpart[tc * 65 + b0 + 0] = e00 + e01;
    rpart[tc * 65 + b0 + 1] = e10 + e11;
    rpart[tc * 65 + b0 + 2] = e20 + e21;
    rpart[tc * 65 + b0 + 3] = e30 + e31;
    __syncthreads();
    if (tid < BB) {
        float s = 0.f;
#pragma unroll
        for (int t2 = 0; t2 < 16; t2++) s += rpart[t2 * 65 + tid];
        g_psum[(size_t)tid * TILES5 + blockIdx.x] = s;
    }
}

// ---------------- kernel 6: scale exp by 1/rowsum ----------------
__global__ void k6_scale(float* __restrict__ out) {
    int b = blockIdx.x, ch = blockIdx.y, t = threadIdx.x;
    __shared__ float sred[8];
    float p = g_psum[(size_t)b * TILES5 + t];        // t < 256 < TILES5
    if (t + 256 < TILES5) p += g_psum[(size_t)b * TILES5 + t + 256];
#pragma unroll
    for (int off = 16; off; off >>= 1)
        p += __shfl_xor_sync(0xffffffffu, p, off);
    if ((t & 31) == 0) sred[t >> 5] = p;
    __syncthreads();
    float tot = ((sred[0] + sred[1]) + (sred[2] + sred[3])) +
                ((sred[4] + sred[5]) + (sred[6] + sred[7]));
    float inv = 1.0f / tot;

    int i = ch * 250 + t;
    if (t < 250) {
        float4 v = ((const float4*)(g_logits + (size_t)b * CC))[i];
        float4 r;
        r.x = v.x * inv; r.y = v.y * inv; r.z = v.z * inv; r.w = v.w * inv;
        ((float4*)(out + (size_t)b * CC))[i] = r;
    }
}

// ---------------- launch ----------------
extern "C" void kernel_launch(void* const* d_in, const int* in_sizes, int n_in,
                              void* d_out, int out_size) {
    const float* stories = (const float*)d_in[0];
    const float* queries = (const float*)d_in[1];
    const float* W1 = (const float*)d_in[2];
    const float* W2 = (const float*)d_in[3];
    const float* W3 = (const float*)d_in[4];
    const float* W4 = (const float*)d_in[5];
    float* out = (float*)d_out;

    k1_reduce_stories<<<BB * MSPLIT + PREF, 256>>>(stories, queries, W1, W2, W3);
    dim3 g3(NSPLIT, 2, 2);
    k3_gemm64<<<g3, 256>>>(queries, W1, W2, W4);
    k4_hops<<<BB, EE>>>(W3);
    k5_logits<<<TILES5, 256>>>(W4);
    dim3 g6(BB, 10);
    k6_scale<<<g6, 256>>>(out);
}

// round 9
// speedup vs baseline: 1.0580x; 1.0187x over previous
#include <cuda_runtime.h>
#include <math.h>

#define BB 64
#define MM 512
#define SS 1024
#define EE 128
#define CC 10000
#define MSPLIT 8
#define NSPLIT 32
#define KCHUNK (SS / NSPLIT)  /* 32 */
#define PREF 8
#define TILES5 313            /* ceil(10000/32) 32-col tiles, one block each */

// ---------------- scratch (device globals; no allocation) ----------------
__device__ __align__(16) float g_partial[BB * MSPLIT * SS];   // 2 MB
__device__ __align__(16) float g_gpart[2 * NSPLIT * BB * EE]; // 2 MB
__device__ __align__(16) float g_uT[EE * BB];                 // u transposed [k][b]
__device__ __align__(16) float g_logits[BB * CC];             // 2.56 MB (exp(logits))
__device__ __align__(16) float g_psum[BB * TILES5];
__device__ __align__(16) float g_dummy[128 * 256];

// ---------------- kernel 1: reduce stories over M + prefetch weights ------------
__global__ void k1_reduce_stories(const float* __restrict__ stories,
                                  const float* __restrict__ queries,
                                  const float* __restrict__ W1,
                                  const float* __restrict__ W2,
                                  const float* __restrict__ W3) {
    int blk = blockIdx.x;
    int t = threadIdx.x;

    if (blk >= BB * MSPLIT) {  // ---- L2 prefetch blocks ----
        int lane = (blk - BB * MSPLIT) * 256 + t;
        float s = 0.f;
        const float4* a = (const float4*)W1;
        for (int i = lane; i < 32768; i += PREF * 256) {
            float4 v = __ldcg(&a[i]); s += v.x + v.y + v.z + v.w;
        }
        a = (const float4*)W2;
        for (int i = lane; i < 32768; i += PREF * 256) {
            float4 v = __ldcg(&a[i]); s += v.x + v.y + v.z + v.w;
        }
        a = (const float4*)queries;
        for (int i = lane; i < 16384; i += PREF * 256) {
            float4 v = __ldcg(&a[i]); s += v.x + v.y + v.z + v.w;
        }
        a = (const float4*)W3;
        for (int i = lane; i < 4096; i += PREF * 256) {
            float4 v = __ldcg(&a[i]); s += v.x + v.y + v.z + v.w;
        }
        g_dummy[lane] = s;
        return;
    }

    int b = blk / MSPLIT, ms = blk % MSPLIT;
    const float4* src =
        (const float4*)(stories + (size_t)(b * MM + ms * (MM / MSPLIT)) * SS);
    float4 a0 = make_float4(0.f, 0.f, 0.f, 0.f);
    float4 a1 = a0, a2 = a0, a3 = a0;
#pragma unroll 4
    for (int m = 0; m < MM / MSPLIT; m += 4) {
        float4 v0 = __ldcs(&src[(size_t)(m + 0) * (SS / 4) + t]);
        float4 v1 = __ldcs(&src[(size_t)(m + 1) * (SS / 4) + t]);
        float4 v2 = __ldcs(&src[(size_t)(m + 2) * (SS / 4) + t]);
        float4 v3 = __ldcs(&src[(size_t)(m + 3) * (SS / 4) + t]);
        a0.x += v0.x; a0.y += v0.y; a0.z += v0.z; a0.w += v0.w;
        a1.x += v1.x; a1.y += v1.y; a1.z += v1.z; a1.w += v1.w;
        a2.x += v2.x; a2.y += v2.y; a2.z += v2.z; a2.w += v2.w;
        a3.x += v3.x; a3.y += v3.y; a3.z += v3.z; a3.w += v3.w;
    }
    float4 r;
    r.x = (a0.x + a1.x) + (a2.x + a3.x);
    r.y = (a0.y + a1.y) + (a2.y + a3.y);
    r.z = (a0.z + a1.z) + (a2.z + a3.z);
    r.w = (a0.w + a1.w) + (a2.w + a3.w);
    ((float4*)g_partial)[(size_t)blk * (SS / 4) + t] = r;
}

// ---------------- kernel 3: u0 = queries@W1^T, o = ssum@W2^T (split-K x32) ------
__global__ void k3_gemm64(const float* __restrict__ queries,
                          const float* __restrict__ W1,
                          const float* __restrict__ W2,
                          const float* __restrict__ W4) {
    int ks = blockIdx.x;
    int eh = blockIdx.y;
    int which = blockIdx.z;
    const float* W = which ? W2 : W1;
    int kbase = ks * KCHUNK;

    // W4 L2 prefetch for k5 across 128 blocks
    int bid = ks + NSPLIT * eh + NSPLIT * 2 * which;  // 0..127
    int plane = bid * 256 + threadIdx.x;
    float ps = 0.f;
    const float4* w4 = (const float4*)W4;
    for (int i = plane; i < 320000; i += 128 * 256) {
        float4 v = __ldcg(&w4[i]); ps += v.x + v.y + v.z + v.w;
    }

    __shared__ __align__(16) float Xs[32][68];
    __shared__ __align__(16) float Ws[32][68];

    int tid = threadIdx.x;
    int tb = tid & 15, te = tid >> 4;
    int lrow = tid >> 3, lkq = tid & 7;

    float acc[16];
#pragma unroll
    for (int i = 0; i < 16; i++) acc[i] = 0.f;

    {
#pragma unroll
        for (int h = 0; h < 2; h++) {
            int row = lrow + 32 * h;
            float4 xv;
            if (which == 0) {
                xv = *(const float4*)&queries[(size_t)row * SS + kbase + lkq * 4];
            } else {
                xv = make_float4(0.f, 0.f, 0.f, 0.f);
#pragma unroll
                for (int msp = 0; msp < MSPLIT; msp++) {
                    float4 v = *(const float4*)&g_partial[
                        (size_t)(row * MSPLIT + msp) * SS + kbase + lkq * 4];
                    xv.x += v.x; xv.y += v.y; xv.z += v.z; xv.w += v.w;
                }
            }
            float4 wv = *(const float4*)&W[(size_t)(eh * 64 + row) * SS + kbase + lkq * 4];
            Xs[lkq * 4 + 0][row] = xv.x; Xs[lkq * 4 + 1][row] = xv.y;
            Xs[lkq * 4 + 2][row] = xv.z; Xs[lkq * 4 + 3][row] = xv.w;
            Ws[lkq * 4 + 0][row] = wv.x; Ws[lkq * 4 + 1][row] = wv.y;
            Ws[lkq * 4 + 2][row] = wv.z; Ws[lkq * 4 + 3][row] = wv.w;
        }
        __syncthreads();
#pragma unroll
        for (int k = 0; k < 32; k++) {
            float4 xv = *(const float4*)&Xs[k][tb * 4];
            float4 wv = *(const float4*)&Ws[k][te * 4];
            acc[0]  += xv.x * wv.x; acc[1]  += xv.x * wv.y;
            acc[2]  += xv.x * wv.z; acc[3]  += xv.x * wv.w;
            acc[4]  += xv.y * wv.x; acc[5]  += xv.y * wv.y;
            acc[6]  += xv.y * wv.z; acc[7]  += xv.y * wv.w;
            acc[8]  += xv.z * wv.x; acc[9]  += xv.z * wv.y;
            acc[10] += xv.z * wv.z; acc[11] += xv.z * wv.w;
            acc[12] += xv.w * wv.x; acc[13] += xv.w * wv.y;
            acc[14] += xv.w * wv.z; acc[15] += xv.w * wv.w;
        }
    }
#pragma unroll
    for (int i = 0; i < 4; i++)
#pragma unroll
        for (int j = 0; j < 4; j++)
            g_gpart[(size_t)((which * NSPLIT + ks) * BB + tb * 4 + i) * EE +
                    eh * 64 + te * 4 + j] = acc[i * 4 + j];
    g_dummy[plane] = ps;
}

// ---------------- kernel 4: split-K combine + 3 hops + L2 norm; writes uT -------
__global__ void k4_hops(const float* __restrict__ W3) {
    __shared__ float us[EE];
    __shared__ float red[4];
    int b = blockIdx.x;
    int f = threadIdx.x;

    float4 w[32];
    const float4* wrow = (const float4*)(W3 + (size_t)f * EE);
#pragma unroll
    for (int q = 0; q < 32; q++) w[q] = __ldcg(&wrow[q]);

    float u = 0.f, o = 0.f;
#pragma unroll
    for (int ks = 0; ks < NSPLIT; ks++) {
        u += g_gpart[(size_t)(ks * BB + b) * EE + f];
        o += g_gpart[(size_t)((NSPLIT + ks) * BB + b) * EE + f];
    }
    us[f] = u;
    __syncthreads();

    float vout = 0.f;
    const float4* us4 = (const float4*)us;
    for (int hop = 0; hop < 3; hop++) {
        float v0 = 0.f, v1 = 0.f, v2 = 0.f, v3 = 0.f;
#pragma unroll
        for (int q = 0; q < 32; q++) {
            float4 uu = us4[q];
            v0 += w[q].x * uu.x;
            v1 += w[q].y * uu.y;
            v2 += w[q].z * uu.z;
            v3 += w[q].w * uu.w;
        }
        float v = o + ((v0 + v1) + (v2 + v3));
        float s = v * v;
#pragma unroll
        for (int off = 16; off; off >>= 1)
            s += __shfl_xor_sync(0xffffffffu, s, off);
        if ((f & 31) == 0) red[f >> 5] = s;
        __syncthreads();
        float tot = (red[0] + red[1]) + (red[2] + red[3]);
        float nrm = fmaxf(sqrtf(tot), 1e-12f);
        vout = v / nrm;
        us[f] = vout;
        __syncthreads();
    }
    g_uT[(size_t)f * BB + b] = vout;  // transposed for k5
}

// ---------------- kernel 5: exp(uT^T @ W4^T), high-ILP 2b x 4c threads ----------
// grid = 313 (one 64b x 32c tile, K=128), block = 256. Thread tile 2b x 4c:
// per k-step 2 LDS feed 8 independent FMAs (self-hiding LDS latency), 2-deep
// software pipeline. XPITCH = 68 (multiple of 4 -> float4 stores stay 16B
// aligned for every k row; 66 crashed with misaligned address).
#define XPITCH 68
#define WPITCH 36
#define K5ROWS 130  /* 128 + 2 pipeline over-read rows */
__global__ void __launch_bounds__(256) k5_logits(const float* __restrict__ W4) {
    __shared__ __align__(16) float Xs[K5ROWS * XPITCH];
    __shared__ __align__(16) float Ws[K5ROWS * WPITCH];
    __shared__ float rpart[8 * 66];

    int tid = threadIdx.x;
    int c0 = blockIdx.x * 32;

    // ---- load Xs: coalesced copy of g_uT [128][64] ----
    {
        const float4* usrc = (const float4*)g_uT;
#pragma unroll
        for (int it = 0; it < 8; it++) {
            int j = tid + 256 * it;        // float4 index 0..2047
            int k = j >> 4, b4 = j & 15;   // 16 float4 per k-row
            float4 v = usrc[j];
            *(float4*)&Xs[k * XPITCH + b4 * 4] = v;
        }
    }
    // ---- load Ws: W4 tile [c][k] -> [k][c], 32 cols ----
    {
        int c = tid & 31;
        int h = tid >> 5;   // 0..7
        int crow = c0 + c;
        bool valid = crow < CC;
        const float4* wsrc = (const float4*)(W4 + (size_t)crow * EE);
#pragma unroll
        for (int j = 0; j < 4; j++) {
            int q = h + 8 * j;  // k-quad 0..31
            float4 wv = make_float4(0.f, 0.f, 0.f, 0.f);
            if (valid) wv = wsrc[q];
            Ws[(4 * q + 0) * WPITCH + c] = wv.x;
            Ws[(4 * q + 1) * WPITCH + c] = wv.y;
            Ws[(4 * q + 2) * WPITCH + c] = wv.z;
            Ws[(4 * q + 3) * WPITCH + c] = wv.w;
        }
    }
    __syncthreads();

    int tc = tid & 7;    // col quad: cols tc*4..+3
    int tb = tid >> 3;   // row pair: rows tb*2, tb*2+1
    const float* xbase = Xs + tb * 2;
    const float* wbase = Ws + tc * 4;

    float a00 = 0.f, a01 = 0.f, a02 = 0.f, a03 = 0.f;
    float a10 = 0.f, a11 = 0.f, a12 = 0.f, a13 = 0.f;

    float2 xa = *(const float2*)(xbase);
    float4 wa = *(const float4*)(wbase);
    float2 xb = *(const float2*)(xbase + XPITCH);
    float4 wb = *(const float4*)(wbase + WPITCH);
#pragma unroll 8
    for (int k = 0; k < EE; k += 2) {
        float2 xc = *(const float2*)(xbase + (k + 2) * XPITCH);
        float4 wc = *(const float4*)(wbase + (k + 2) * WPITCH);
        a00 += xa.x * wa.x; a01 += xa.x * wa.y;
        a02 += xa.x * wa.z; a03 += xa.x * wa.w;
        a10 += xa.y * wa.x; a11 += xa.y * wa.y;
        a12 += xa.y * wa.z; a13 += xa.y * wa.w;
        float2 xd = *(const float2*)(xbase + (k + 3) * XPITCH);
        float4 wd = *(const float4*)(wbase + (k + 3) * WPITCH);
        a00 += xb.x * wb.x; a01 += xb.x * wb.y;
        a02 += xb.x * wb.z; a03 += xb.x * wb.w;
        a10 += xb.y * wb.x; a11 += xb.y * wb.y;
        a12 += xb.y * wb.z; a13 += xb.y * wb.w;
        xa = xc; wa = wc;
        xb = xd; wb = wd;
    }

    // ---- epilogue: exp, coalesced float4 stores, per-tile row partials ----
    int cA = c0 + tc * 4;
    bool valid = cA < CC;  // CC % 4 == 0 -> whole quad valid or invalid
    float e00 = valid ? __expf(a00) : 0.f, e01 = valid ? __expf(a01) : 0.f;
    float e02 = valid ? __expf(a02) : 0.f, e03 = valid ? __expf(a03) : 0.f;
    float e10 = valid ? __expf(a10) : 0.f, e11 = valid ? __expf(a11) : 0.f;
    float e12 = valid ? __expf(a12) : 0.f, e13 = valid ? __expf(a13) : 0.f;
    int r0 = tb * 2, r1 = r0 + 1;
    if (valid) {
        *(float4*)&g_logits[(size_t)r0 * CC + cA] = make_float4(e00, e01, e02, e03);
        *(float4*)&g_logits[(size_t)r1 * CC + cA] = make_float4(e10, e11, e12, e13);
    }
    rpart[tc * 66 + r0] = (e00 + e01) + (e02 + e03);
    rpart[tc * 66 + r1] = (e10 + e11) + (e12 + e13);
    __syncthreads();
    if (tid < BB) {
        float s = 0.f;
#pragma unroll
        for (int t2 = 0; t2 < 8; t2++) s += rpart[t2 * 66 + tid];
        g_psum[(size_t)tid * TILES5 + blockIdx.x] = s;
    }
}

// ---------------- kernel 6: scale exp by 1/rowsum ----------------
__global__ void k6_scale(float* __restrict__ out) {
    int b = blockIdx.x, ch = blockIdx.y, t = threadIdx.x;
    __shared__ float sred[8];
    float p = g_psum[(size_t)b * TILES5 + t];        // t < 256 < TILES5
    if (t + 256 < TILES5) p += g_psum[(size_t)b * TILES5 + t + 256];
#pragma unroll
    for (int off = 16; off; off >>= 1)
        p += __shfl_xor_sync(0xffffffffu, p, off);
    if ((t & 31) == 0) sred[t >> 5] = p;
    __syncthreads();
    float tot = ((sred[0] + sred[1]) + (sred[2] + sred[3])) +
                ((sred[4] + sred[5]) + (sred[6] + sred[7]));
    float inv = 1.0f / tot;

    int i = ch * 250 + t;
    if (t < 250) {
        float4 v = ((const float4*)(g_logits + (size_t)b * CC))[i];
        float4 r;
        r.x = v.x * inv; r.y = v.y * inv; r.z = v.z * inv; r.w = v.w * inv;
        ((float4*)(out + (size_t)b * CC))[i] = r;
    }
}

// ---------------- launch ----------------
extern "C" void kernel_launch(void* const* d_in, const int* in_sizes, int n_in,
                              void* d_out, int out_size) {
    const float* stories = (const float*)d_in[0];
    const float* queries = (const float*)d_in[1];
    const float* W1 = (const float*)d_in[2];
    const float* W2 = (const float*)d_in[3];
    const float* W3 = (const float*)d_in[4];
    const float* W4 = (const float*)d_in[5];
    float* out = (float*)d_out;

    k1_reduce_stories<<<BB * MSPLIT + PREF, 256>>>(stories, queries, W1, W2, W3);
    dim3 g3(NSPLIT, 2, 2);
    k3_gemm64<<<g3, 256>>>(queries, W1, W2, W4);
    k4_hops<<<BB, EE>>>(W3);
    k5_logits<<<TILES5, 256>>>(W4);
    dim3 g6(BB, 10);
    k6_scale<<<g6, 256>>>(out);
}

// round 10
// speedup vs baseline: 1.1641x; 1.1003x over previous
#include <cuda_runtime.h>
#include <math.h>
#include <stdint.h>

#define BB 64
#define MM 512
#define SS 1024
#define EE 128
#define CC 10000
#define MSPLIT 8
#define NSPLIT 32
#define KCHUNK (SS / NSPLIT)  /* 32 */
#define PREF 8
#define TILES5 157            /* ceil(10000/64) 64-col tiles, one block each */

// ---------------- scratch (device globals; no allocation) ----------------
__device__ __align__(16) float g_partial[BB * MSPLIT * SS];   // 2 MB
__device__ __align__(16) float g_gpart[2 * NSPLIT * BB * EE]; // 2 MB
__device__ __align__(16) float g_uafrag[BB * EE];             // A fragments, mma order
__device__ __align__(16) float g_logits[BB * CC];             // 2.56 MB (exp(logits))
__device__ __align__(16) float g_psum[BB * TILES5];
__device__ __align__(16) float g_dummy[128 * 256];

// ---------------- kernel 1: reduce stories over M + prefetch weights ------------
__global__ void k1_reduce_stories(const float* __restrict__ stories,
                                  const float* __restrict__ queries,
                                  const float* __restrict__ W1,
                                  const float* __restrict__ W2,
                                  const float* __restrict__ W3) {
    int blk = blockIdx.x;
    int t = threadIdx.x;

    if (blk >= BB * MSPLIT) {  // ---- L2 prefetch blocks ----
        int lane = (blk - BB * MSPLIT) * 256 + t;
        float s = 0.f;
        const float4* a = (const float4*)W1;
        for (int i = lane; i < 32768; i += PREF * 256) {
            float4 v = __ldcg(&a[i]); s += v.x + v.y + v.z + v.w;
        }
        a = (const float4*)W2;
        for (int i = lane; i < 32768; i += PREF * 256) {
            float4 v = __ldcg(&a[i]); s += v.x + v.y + v.z + v.w;
        }
        a = (const float4*)queries;
        for (int i = lane; i < 16384; i += PREF * 256) {
            float4 v = __ldcg(&a[i]); s += v.x + v.y + v.z + v.w;
        }
        a = (const float4*)W3;
        for (int i = lane; i < 4096; i += PREF * 256) {
            float4 v = __ldcg(&a[i]); s += v.x + v.y + v.z + v.w;
        }
        g_dummy[lane] = s;
        return;
    }

    int b = blk / MSPLIT, ms = blk % MSPLIT;
    const float4* src =
        (const float4*)(stories + (size_t)(b * MM + ms * (MM / MSPLIT)) * SS);
    float4 a0 = make_float4(0.f, 0.f, 0.f, 0.f);
    float4 a1 = a0, a2 = a0, a3 = a0;
#pragma unroll 4
    for (int m = 0; m < MM / MSPLIT; m += 4) {
        float4 v0 = __ldcs(&src[(size_t)(m + 0) * (SS / 4) + t]);
        float4 v1 = __ldcs(&src[(size_t)(m + 1) * (SS / 4) + t]);
        float4 v2 = __ldcs(&src[(size_t)(m + 2) * (SS / 4) + t]);
        float4 v3 = __ldcs(&src[(size_t)(m + 3) * (SS / 4) + t]);
        a0.x += v0.x; a0.y += v0.y; a0.z += v0.z; a0.w += v0.w;
        a1.x += v1.x; a1.y += v1.y; a1.z += v1.z; a1.w += v1.w;
        a2.x += v2.x; a2.y += v2.y; a2.z += v2.z; a2.w += v2.w;
        a3.x += v3.x; a3.y += v3.y; a3.z += v3.z; a3.w += v3.w;
    }
    float4 r;
    r.x = (a0.x + a1.x) + (a2.x + a3.x);
    r.y = (a0.y + a1.y) + (a2.y + a3.y);
    r.z = (a0.z + a1.z) + (a2.z + a3.z);
    r.w = (a0.w + a1.w) + (a2.w + a3.w);
    ((float4*)g_partial)[(size_t)blk * (SS / 4) + t] = r;
}

// ---------------- kernel 3: u0 = queries@W1^T, o = ssum@W2^T (split-K x32) ------
__global__ void k3_gemm64(const float* __restrict__ queries,
                          const float* __restrict__ W1,
                          const float* __restrict__ W2,
                          const float* __restrict__ W4) {
    int ks = blockIdx.x;
    int eh = blockIdx.y;
    int which = blockIdx.z;
    const float* W = which ? W2 : W1;
    int kbase = ks * KCHUNK;

    // W4 L2 prefetch for k5 across 128 blocks
    int bid = ks + NSPLIT * eh + NSPLIT * 2 * which;  // 0..127
    int plane = bid * 256 + threadIdx.x;
    float ps = 0.f;
    const float4* w4 = (const float4*)W4;
    for (int i = plane; i < 320000; i += 128 * 256) {
        float4 v = __ldcg(&w4[i]); ps += v.x + v.y + v.z + v.w;
    }

    __shared__ __align__(16) float Xs[32][68];
    __shared__ __align__(16) float Ws[32][68];

    int tid = threadIdx.x;
    int tb = tid & 15, te = tid >> 4;
    int lrow = tid >> 3, lkq = tid & 7;

    float acc[16];
#pragma unroll
    for (int i = 0; i < 16; i++) acc[i] = 0.f;

    {
#pragma unroll
        for (int h = 0; h < 2; h++) {
            int row = lrow + 32 * h;
            float4 xv;
            if (which == 0) {
                xv = *(const float4*)&queries[(size_t)row * SS + kbase + lkq * 4];
            } else {
                xv = make_float4(0.f, 0.f, 0.f, 0.f);
#pragma unroll
                for (int msp = 0; msp < MSPLIT; msp++) {
                    float4 v = *(const float4*)&g_partial[
                        (size_t)(row * MSPLIT + msp) * SS + kbase + lkq * 4];
                    xv.x += v.x; xv.y += v.y; xv.z += v.z; xv.w += v.w;
                }
            }
            float4 wv = *(const float4*)&W[(size_t)(eh * 64 + row) * SS + kbase + lkq * 4];
            Xs[lkq * 4 + 0][row] = xv.x; Xs[lkq * 4 + 1][row] = xv.y;
            Xs[lkq * 4 + 2][row] = xv.z; Xs[lkq * 4 + 3][row] = xv.w;
            Ws[lkq * 4 + 0][row] = wv.x; Ws[lkq * 4 + 1][row] = wv.y;
            Ws[lkq * 4 + 2][row] = wv.z; Ws[lkq * 4 + 3][row] = wv.w;
        }
        __syncthreads();
#pragma unroll
        for (int k = 0; k < 32; k++) {
            float4 xv = *(const float4*)&Xs[k][tb * 4];
            float4 wv = *(const float4*)&Ws[k][te * 4];
            acc[0]  += xv.x * wv.x; acc[1]  += xv.x * wv.y;
            acc[2]  += xv.x * wv.z; acc[3]  += xv.x * wv.w;
            acc[4]  += xv.y * wv.x; acc[5]  += xv.y * wv.y;
            acc[6]  += xv.y * wv.z; acc[7]  += xv.y * wv.w;
            acc[8]  += xv.z * wv.x; acc[9]  += xv.z * wv.y;
            acc[10] += xv.z * wv.z; acc[11] += xv.z * wv.w;
            acc[12] += xv.w * wv.x; acc[13] += xv.w * wv.y;
            acc[14] += xv.w * wv.z; acc[15] += xv.w * wv.w;
        }
    }
#pragma unroll
    for (int i = 0; i < 4; i++)
#pragma unroll
        for (int j = 0; j < 4; j++)
            g_gpart[(size_t)((which * NSPLIT + ks) * BB + tb * 4 + i) * EE +
                    eh * 64 + te * 4 + j] = acc[i * 4 + j];
    g_dummy[plane] = ps;
}

// ---------------- kernel 4: split-K combine + hops + norm; writes A-frags -------
// Final u written as tf32-rounded mma A-fragments (m16n8k8 layout):
// a0=(g,t) a1=(g+8,t) a2=(g,t+4) a3=(g+8,t+4), lane = g*4+t.
__global__ void k4_hops(const float* __restrict__ W3) {
    __shared__ float us[EE];
    __shared__ float red[4];
    int b = blockIdx.x;
    int f = threadIdx.x;

    float4 w[32];
    const float4* wrow = (const float4*)(W3 + (size_t)f * EE);
#pragma unroll
    for (int q = 0; q < 32; q++) w[q] = __ldcg(&wrow[q]);

    float u = 0.f, o = 0.f;
#pragma unroll
    for (int ks = 0; ks < NSPLIT; ks++) {
        u += g_gpart[(size_t)(ks * BB + b) * EE + f];
        o += g_gpart[(size_t)((NSPLIT + ks) * BB + b) * EE + f];
    }
    us[f] = u;
    __syncthreads();

    float vout = 0.f;
    const float4* us4 = (const float4*)us;
    for (int hop = 0; hop < 3; hop++) {
        float v0 = 0.f, v1 = 0.f, v2 = 0.f, v3 = 0.f;
#pragma unroll
        for (int q = 0; q < 32; q++) {
            float4 uu = us4[q];
            v0 += w[q].x * uu.x;
            v1 += w[q].y * uu.y;
            v2 += w[q].z * uu.z;
            v3 += w[q].w * uu.w;
        }
        float v = o + ((v0 + v1) + (v2 + v3));
        float s = v * v;
#pragma unroll
        for (int off = 16; off; off >>= 1)
            s += __shfl_xor_sync(0xffffffffu, s, off);
        if ((f & 31) == 0) red[f >> 5] = s;
        __syncthreads();
        float tot = (red[0] + red[1]) + (red[2] + red[3]);
        float nrm = fmaxf(sqrtf(tot), 1e-12f);
        vout = v / nrm;
        us[f] = vout;
        __syncthreads();
    }

    // scatter into mma A-fragment order, tf32-rounded
    int wm = b >> 4, r = b & 15, rh = r >> 3, g = r & 7;
    int kstep = f >> 3, kt = f & 7, ch = kt >> 2, t = kt & 3;
    uint32_t bits;
    asm("cvt.rna.tf32.f32 %0, %1;" : "=r"(bits) : "f"(vout));
    g_uafrag[(size_t)(((wm * 16 + kstep) * 32 + (g * 4 + t)) * 4) + (ch * 2 + rh)] =
        __uint_as_float(bits);
}

// ---------------- kernel 5: exp(u @ W4^T) via tf32 tensor-core mma --------------
// grid = 157 (64b x 64c tile, K=128 = 16 mma.m16n8k8 steps), block = 256 (8 warps
// = 4 m-strips x 2 n-halves; warp tile m16 x n32 = 4 n8 tiles).
#define WPITCH5 132
__global__ void __launch_bounds__(256) k5_logits(const float* __restrict__ W4) {
    extern __shared__ float sm5[];
    float* As = sm5;                       // 8192 floats: A fragments
    float* Ws = sm5 + 8192;                // 64 x 132
    float* rpart = sm5 + 8192 + 64 * WPITCH5;  // 2 x 66

    int tid = threadIdx.x;
    int c0 = blockIdx.x * 64;

    // ---- stage A fragments (straight copy) ----
    {
        const float4* af = (const float4*)g_uafrag;
        float4* ad = (float4*)As;
#pragma unroll
        for (int i = 0; i < 8; i++) ad[tid + 256 * i] = af[tid + 256 * i];
    }
    // ---- stage W4 tile [c][k] with tf32 rounding ----
    {
        int c = tid >> 2, kq = tid & 3;
        int crow = c0 + c;
        bool valid = crow < CC;
        const float4* wsrc = (const float4*)(W4 + (size_t)crow * EE);
#pragma unroll
        for (int i = 0; i < 8; i++) {
            float4 wv = make_float4(0.f, 0.f, 0.f, 0.f);
            if (valid) wv = wsrc[kq * 8 + i];
            uint32_t q0, q1, q2, q3;
            asm("cvt.rna.tf32.f32 %0, %1;" : "=r"(q0) : "f"(wv.x));
            asm("cvt.rna.tf32.f32 %0, %1;" : "=r"(q1) : "f"(wv.y));
            asm("cvt.rna.tf32.f32 %0, %1;" : "=r"(q2) : "f"(wv.z));
            asm("cvt.rna.tf32.f32 %0, %1;" : "=r"(q3) : "f"(wv.w));
            *(float4*)&Ws[c * WPITCH5 + kq * 32 + i * 4] =
                make_float4(__uint_as_float(q0), __uint_as_float(q1),
                            __uint_as_float(q2), __uint_as_float(q3));
        }
    }
    __syncthreads();

    int w = tid >> 5, l = tid & 31;
    int wm = w & 3, wn = w >> 2;
    int g = l >> 2, t = l & 3;

    float acc[4][4];
#pragma unroll
    for (int i = 0; i < 4; i++)
#pragma unroll
        for (int j = 0; j < 4; j++) acc[i][j] = 0.f;

#pragma unroll
    for (int ks = 0; ks < 16; ks++) {
        float4 av = ((const float4*)As)[(wm * 16 + ks) * 32 + l];
        uint32_t a0 = __float_as_uint(av.x), a1 = __float_as_uint(av.y);
        uint32_t a2 = __float_as_uint(av.z), a3 = __float_as_uint(av.w);
#pragma unroll
        for (int tile = 0; tile < 4; tile++) {
            int cc = wn * 32 + tile * 8 + g;
            uint32_t b0 = __float_as_uint(Ws[cc * WPITCH5 + ks * 8 + t]);
            uint32_t b1 = __float_as_uint(Ws[cc * WPITCH5 + ks * 8 + t + 4]);
            asm volatile(
                "mma.sync.aligned.m16n8k8.row.col.f32.tf32.tf32.f32 "
                "{%0,%1,%2,%3}, {%4,%5,%6,%7}, {%8,%9}, {%0,%1,%2,%3};"
                : "+f"(acc[tile][0]), "+f"(acc[tile][1]),
                  "+f"(acc[tile][2]), "+f"(acc[tile][3])
                : "r"(a0), "r"(a1), "r"(a2), "r"(a3), "r"(b0), "r"(b1));
        }
    }

    // ---- epilogue: exp, float2 stores, row partial sums ----
    int row0 = wm * 16 + g, row1 = row0 + 8;
    float s0 = 0.f, s1 = 0.f;
#pragma unroll
    for (int tile = 0; tile < 4; tile++) {
        int cc = c0 + wn * 32 + tile * 8 + 2 * t;
        bool valid = cc < CC;  // CC even -> pair valid together
        float e0 = valid ? __expf(acc[tile][0]) : 0.f;
        float e1 = valid ? __expf(acc[tile][1]) : 0.f;
        float e2 = valid ? __expf(acc[tile][2]) : 0.f;
        float e3 = valid ? __expf(acc[tile][3]) : 0.f;
        if (valid) {
            *(float2*)&g_logits[(size_t)row0 * CC + cc] = make_float2(e0, e1);
            *(float2*)&g_logits[(size_t)row1 * CC + cc] = make_float2(e2, e3);
        }
        s0 += e0 + e1;
        s1 += e2 + e3;
    }
    s0 += __shfl_xor_sync(0xffffffffu, s0, 1);
    s0 += __shfl_xor_sync(0xffffffffu, s0, 2);
    s1 += __shfl_xor_sync(0xffffffffu, s1, 1);
    s1 += __shfl_xor_sync(0xffffffffu, s1, 2);
    if (t == 0) {
        rpart[wn * 66 + row0] = s0;
        rpart[wn * 66 + row1] = s1;
    }
    __syncthreads();
    if (tid < BB) {
        g_psum[(size_t)tid * TILES5 + blockIdx.x] =
            rpart[tid] + rpart[66 + tid];
    }
}

// ---------------- kernel 6: scale exp by 1/rowsum ----------------
__global__ void k6_scale(float* __restrict__ out) {
    int b = blockIdx.x, ch = blockIdx.y, t = threadIdx.x;
    __shared__ float sred[8];
    float p = (t < TILES5) ? g_psum[(size_t)b * TILES5 + t] : 0.f;
#pragma unroll
    for (int off = 16; off; off >>= 1)
        p += __shfl_xor_sync(0xffffffffu, p, off);
    if ((t & 31) == 0) sred[t >> 5] = p;
    __syncthreads();
    float tot = ((sred[0] + sred[1]) + (sred[2] + sred[3])) +
                ((sred[4] + sred[5]) + (sred[6] + sred[7]));
    float inv = 1.0f / tot;

    int i = ch * 250 + t;
    if (t < 250) {
        float4 v = ((const float4*)(g_logits + (size_t)b * CC))[i];
        float4 r;
        r.x = v.x * inv; r.y = v.y * inv; r.z = v.z * inv; r.w = v.w * inv;
        ((float4*)(out + (size_t)b * CC))[i] = r;
    }
}

// ---------------- launch ----------------
extern "C" void kernel_launch(void* const* d_in, const int* in_sizes, int n_in,
                              void* d_out, int out_size) {
    const float* stories = (const float*)d_in[0];
    const float* queries = (const float*)d_in[1];
    const float* W1 = (const float*)d_in[2];
    const float* W2 = (const float*)d_in[3];
    const float* W3 = (const float*)d_in[4];
    const float* W4 = (const float*)d_in[5];
    float* out = (float*)d_out;

    static int k5_smem = 0;
    int smem5 = (8192 + 64 * WPITCH5 + 2 * 66) * 4;  // ~66 KB
    if (!k5_smem) {
        cudaFuncSetAttribute(k5_logits,
                             cudaFuncAttributeMaxDynamicSharedMemorySize, smem5);
        k5_smem = 1;
    }

    k1_reduce_stories<<<BB * MSPLIT + PREF, 256>>>(stories, queries, W1, W2, W3);
    dim3 g3(NSPLIT, 2, 2);
    k3_gemm64<<<g3, 256>>>(queries, W1, W2, W4);
    k4_hops<<<BB, EE>>>(W3);
    k5_logits<<<TILES5, 256, smem5>>>(W4);
    dim3 g6(BB, 10);
    k6_scale<<<g6, 256>>>(out);
}

// round 11
// speedup vs baseline: 1.1918x; 1.0238x over previous
#include <cuda_runtime.h>
#include <math.h>
#include <stdint.h>

#define BB 64
#define MM 512
#define SS 1024
#define EE 128
#define CC 10000
#define MSPLIT 8
#define NSPLIT 32
#define KCHUNK (SS / NSPLIT)  /* 32 */
#define PREF 8
#define TILES5 313            /* ceil(10000/32) 32-col tiles, one block each */

// ---------------- scratch (device globals; no allocation) ----------------
__device__ __align__(16) float g_partial[BB * MSPLIT * SS];   // 2 MB
__device__ __align__(16) float g_gpart[2 * NSPLIT * BB * EE]; // 2 MB
__device__ __align__(16) float g_uafrag[BB * EE];             // A fragments, mma order
__device__ __align__(16) float g_logits[BB * CC];             // 2.56 MB (exp(logits))
__device__ __align__(16) float g_psum[BB * TILES5];
__device__ __align__(16) float g_dummy[128 * 256];

// ---------------- kernel 1: reduce stories over M + prefetch weights ------------
__global__ void k1_reduce_stories(const float* __restrict__ stories,
                                  const float* __restrict__ queries,
                                  const float* __restrict__ W1,
                                  const float* __restrict__ W2,
                                  const float* __restrict__ W3) {
    int blk = blockIdx.x;
    int t = threadIdx.x;

    if (blk >= BB * MSPLIT) {  // ---- L2 prefetch blocks ----
        int lane = (blk - BB * MSPLIT) * 256 + t;
        float s = 0.f;
        const float4* a = (const float4*)W1;
        for (int i = lane; i < 32768; i += PREF * 256) {
            float4 v = __ldcg(&a[i]); s += v.x + v.y + v.z + v.w;
        }
        a = (const float4*)W2;
        for (int i = lane; i < 32768; i += PREF * 256) {
            float4 v = __ldcg(&a[i]); s += v.x + v.y + v.z + v.w;
        }
        a = (const float4*)queries;
        for (int i = lane; i < 16384; i += PREF * 256) {
            float4 v = __ldcg(&a[i]); s += v.x + v.y + v.z + v.w;
        }
        a = (const float4*)W3;
        for (int i = lane; i < 4096; i += PREF * 256) {
            float4 v = __ldcg(&a[i]); s += v.x + v.y + v.z + v.w;
        }
        g_dummy[lane] = s;
        return;
    }

    int b = blk / MSPLIT, ms = blk % MSPLIT;
    const float4* src =
        (const float4*)(stories + (size_t)(b * MM + ms * (MM / MSPLIT)) * SS);
    float4 a0 = make_float4(0.f, 0.f, 0.f, 0.f);
    float4 a1 = a0, a2 = a0, a3 = a0;
#pragma unroll 4
    for (int m = 0; m < MM / MSPLIT; m += 4) {
        float4 v0 = __ldcs(&src[(size_t)(m + 0) * (SS / 4) + t]);
        float4 v1 = __ldcs(&src[(size_t)(m + 1) * (SS / 4) + t]);
        float4 v2 = __ldcs(&src[(size_t)(m + 2) * (SS / 4) + t]);
        float4 v3 = __ldcs(&src[(size_t)(m + 3) * (SS / 4) + t]);
        a0.x += v0.x; a0.y += v0.y; a0.z += v0.z; a0.w += v0.w;
        a1.x += v1.x; a1.y += v1.y; a1.z += v1.z; a1.w += v1.w;
        a2.x += v2.x; a2.y += v2.y; a2.z += v2.z; a2.w += v2.w;
        a3.x += v3.x; a3.y += v3.y; a3.z += v3.z; a3.w += v3.w;
    }
    float4 r;
    r.x = (a0.x + a1.x) + (a2.x + a3.x);
    r.y = (a0.y + a1.y) + (a2.y + a3.y);
    r.z = (a0.z + a1.z) + (a2.z + a3.z);
    r.w = (a0.w + a1.w) + (a2.w + a3.w);
    ((float4*)g_partial)[(size_t)blk * (SS / 4) + t] = r;
}

// ---------------- kernel 3: u0 = queries@W1^T, o = ssum@W2^T (split-K x32) ------
__global__ void k3_gemm64(const float* __restrict__ queries,
                          const float* __restrict__ W1,
                          const float* __restrict__ W2,
                          const float* __restrict__ W4) {
    int ks = blockIdx.x;
    int eh = blockIdx.y;
    int which = blockIdx.z;
    const float* W = which ? W2 : W1;
    int kbase = ks * KCHUNK;

    // W4 L2 prefetch for k5 across 128 blocks
    int bid = ks + NSPLIT * eh + NSPLIT * 2 * which;  // 0..127
    int plane = bid * 256 + threadIdx.x;
    float ps = 0.f;
    const float4* w4 = (const float4*)W4;
    for (int i = plane; i < 320000; i += 128 * 256) {
        float4 v = __ldcg(&w4[i]); ps += v.x + v.y + v.z + v.w;
    }

    __shared__ __align__(16) float Xs[32][68];
    __shared__ __align__(16) float Ws[32][68];

    int tid = threadIdx.x;
    int tb = tid & 15, te = tid >> 4;
    int lrow = tid >> 3, lkq = tid & 7;

    float acc[16];
#pragma unroll
    for (int i = 0; i < 16; i++) acc[i] = 0.f;

    {
#pragma unroll
        for (int h = 0; h < 2; h++) {
            int row = lrow + 32 * h;
            float4 xv;
            if (which == 0) {
                xv = *(const float4*)&queries[(size_t)row * SS + kbase + lkq * 4];
            } else {
                xv = make_float4(0.f, 0.f, 0.f, 0.f);
#pragma unroll
                for (int msp = 0; msp < MSPLIT; msp++) {
                    float4 v = *(const float4*)&g_partial[
                        (size_t)(row * MSPLIT + msp) * SS + kbase + lkq * 4];
                    xv.x += v.x; xv.y += v.y; xv.z += v.z; xv.w += v.w;
                }
            }
            float4 wv = *(const float4*)&W[(size_t)(eh * 64 + row) * SS + kbase + lkq * 4];
            Xs[lkq * 4 + 0][row] = xv.x; Xs[lkq * 4 + 1][row] = xv.y;
            Xs[lkq * 4 + 2][row] = xv.z; Xs[lkq * 4 + 3][row] = xv.w;
            Ws[lkq * 4 + 0][row] = wv.x; Ws[lkq * 4 + 1][row] = wv.y;
            Ws[lkq * 4 + 2][row] = wv.z; Ws[lkq * 4 + 3][row] = wv.w;
        }
        __syncthreads();
#pragma unroll
        for (int k = 0; k < 32; k++) {
            float4 xv = *(const float4*)&Xs[k][tb * 4];
            float4 wv = *(const float4*)&Ws[k][te * 4];
            acc[0]  += xv.x * wv.x; acc[1]  += xv.x * wv.y;
            acc[2]  += xv.x * wv.z; acc[3]  += xv.x * wv.w;
            acc[4]  += xv.y * wv.x; acc[5]  += xv.y * wv.y;
            acc[6]  += xv.y * wv.z; acc[7]  += xv.y * wv.w;
            acc[8]  += xv.z * wv.x; acc[9]  += xv.z * wv.y;
            acc[10] += xv.z * wv.z; acc[11] += xv.z * wv.w;
            acc[12] += xv.w * wv.x; acc[13] += xv.w * wv.y;
            acc[14] += xv.w * wv.z; acc[15] += xv.w * wv.w;
        }
    }
#pragma unroll
    for (int i = 0; i < 4; i++)
#pragma unroll
        for (int j = 0; j < 4; j++)
            g_gpart[(size_t)((which * NSPLIT + ks) * BB + tb * 4 + i) * EE +
                    eh * 64 + te * 4 + j] = acc[i * 4 + j];
    g_dummy[plane] = ps;
}

// ---------------- kernel 4: split-K combine + hops + norm; writes A-frags -------
// Final u written as tf32-rounded mma A-fragments (m16n8k8 layout):
// a0=(g,t) a1=(g+8,t) a2=(g,t+4) a3=(g+8,t+4), lane = g*4+t.
__global__ void k4_hops(const float* __restrict__ W3) {
    __shared__ float us[EE];
    __shared__ float red[4];
    int b = blockIdx.x;
    int f = threadIdx.x;

    float4 w[32];
    const float4* wrow = (const float4*)(W3 + (size_t)f * EE);
#pragma unroll
    for (int q = 0; q < 32; q++) w[q] = __ldcg(&wrow[q]);

    float u = 0.f, o = 0.f;
#pragma unroll
    for (int ks = 0; ks < NSPLIT; ks++) {
        u += g_gpart[(size_t)(ks * BB + b) * EE + f];
        o += g_gpart[(size_t)((NSPLIT + ks) * BB + b) * EE + f];
    }
    us[f] = u;
    __syncthreads();

    float vout = 0.f;
    const float4* us4 = (const float4*)us;
    for (int hop = 0; hop < 3; hop++) {
        float v0 = 0.f, v1 = 0.f, v2 = 0.f, v3 = 0.f;
#pragma unroll
        for (int q = 0; q < 32; q++) {
            float4 uu = us4[q];
            v0 += w[q].x * uu.x;
            v1 += w[q].y * uu.y;
            v2 += w[q].z * uu.z;
            v3 += w[q].w * uu.w;
        }
        float v = o + ((v0 + v1) + (v2 + v3));
        float s = v * v;
#pragma unroll
        for (int off = 16; off; off >>= 1)
            s += __shfl_xor_sync(0xffffffffu, s, off);
        if ((f & 31) == 0) red[f >> 5] = s;
        __syncthreads();
        float tot = (red[0] + red[1]) + (red[2] + red[3]);
        float nrm = fmaxf(sqrtf(tot), 1e-12f);
        vout = v / nrm;
        us[f] = vout;
        __syncthreads();
    }

    // scatter into mma A-fragment order, tf32-rounded
    int wm = b >> 4, r = b & 15, rh = r >> 3, g = r & 7;
    int kstep = f >> 3, kt = f & 7, ch = kt >> 2, t = kt & 3;
    uint32_t bits;
    asm("cvt.rna.tf32.f32 %0, %1;" : "=r"(bits) : "f"(vout));
    g_uafrag[(size_t)(((wm * 16 + kstep) * 32 + (g * 4 + t)) * 4) + (ch * 2 + rh)] =
        __uint_as_float(bits);
}

// ---------------- kernel 5: exp(u @ W4^T) via tf32 mma, 2 blocks/SM -------------
// grid = 313 (64b x 32c tile, K=128 = 16 mma steps), block = 256 (8 warps =
// 4 m-strips x 2 n-halves of 16 cols; warp tile m16 x n16 = 2 n8 tiles).
// smem ~50 KB -> 2 resident blocks/SM (16 warps) so prologue overlaps mainloop.
#define WP5 132
__global__ void __launch_bounds__(256) k5_logits(const float* __restrict__ W4) {
    extern __shared__ float sm5[];
    float* As = sm5;                       // 8192 floats: A fragments
    float* Ws = sm5 + 8192;                // 32 x 132
    float* rpart = sm5 + 8192 + 32 * WP5;  // 2 x 66

    int tid = threadIdx.x;
    int c0 = blockIdx.x * 32;

    // ---- stage A fragments (straight copy, 32 KB) ----
    {
        const float4* af = (const float4*)g_uafrag;
        float4* ad = (float4*)As;
#pragma unroll
        for (int i = 0; i < 8; i++) ad[tid + 256 * i] = af[tid + 256 * i];
    }
    // ---- stage W4 tile [c][k] with tf32 rounding (32 cols) ----
    {
        int c = tid >> 3, kq8 = tid & 7;   // col 0..31, k-octant 0..7
        int crow = c0 + c;
        bool valid = crow < CC;
        const float4* wsrc = (const float4*)(W4 + (size_t)crow * EE);
#pragma unroll
        for (int i = 0; i < 4; i++) {
            int q = kq8 * 4 + i;           // k-quad 0..31
            float4 wv = make_float4(0.f, 0.f, 0.f, 0.f);
            if (valid) wv = wsrc[q];
            uint32_t q0, q1, q2, q3;
            asm("cvt.rna.tf32.f32 %0, %1;" : "=r"(q0) : "f"(wv.x));
            asm("cvt.rna.tf32.f32 %0, %1;" : "=r"(q1) : "f"(wv.y));
            asm("cvt.rna.tf32.f32 %0, %1;" : "=r"(q2) : "f"(wv.z));
            asm("cvt.rna.tf32.f32 %0, %1;" : "=r"(q3) : "f"(wv.w));
            *(float4*)&Ws[c * WP5 + q * 4] =
                make_float4(__uint_as_float(q0), __uint_as_float(q1),
                            __uint_as_float(q2), __uint_as_float(q3));
        }
    }
    __syncthreads();

    int w = tid >> 5, l = tid & 31;
    int wm = w & 3, wn = w >> 2;           // 4 m-strips x 2 n-halves
    int g = l >> 2, t = l & 3;

    float acc[2][4];
#pragma unroll
    for (int i = 0; i < 2; i++)
#pragma unroll
        for (int j = 0; j < 4; j++) acc[i][j] = 0.f;

#pragma unroll
    for (int ks = 0; ks < 16; ks++) {
        float4 av = ((const float4*)As)[(wm * 16 + ks) * 32 + l];
        uint32_t a0 = __float_as_uint(av.x), a1 = __float_as_uint(av.y);
        uint32_t a2 = __float_as_uint(av.z), a3 = __float_as_uint(av.w);
#pragma unroll
        for (int tile = 0; tile < 2; tile++) {
            int cc = wn * 16 + tile * 8 + g;
            uint32_t b0 = __float_as_uint(Ws[cc * WP5 + ks * 8 + t]);
            uint32_t b1 = __float_as_uint(Ws[cc * WP5 + ks * 8 + t + 4]);
            asm volatile(
                "mma.sync.aligned.m16n8k8.row.col.f32.tf32.tf32.f32 "
                "{%0,%1,%2,%3}, {%4,%5,%6,%7}, {%8,%9}, {%0,%1,%2,%3};"
                : "+f"(acc[tile][0]), "+f"(acc[tile][1]),
                  "+f"(acc[tile][2]), "+f"(acc[tile][3])
                : "r"(a0), "r"(a1), "r"(a2), "r"(a3), "r"(b0), "r"(b1));
        }
    }

    // ---- epilogue: exp, float2 stores, row partial sums ----
    int row0 = wm * 16 + g, row1 = row0 + 8;
    float s0 = 0.f, s1 = 0.f;
#pragma unroll
    for (int tile = 0; tile < 2; tile++) {
        int cc = c0 + wn * 16 + tile * 8 + 2 * t;
        bool valid = cc < CC;  // CC even -> pair valid together
        float e0 = valid ? __expf(acc[tile][0]) : 0.f;
        float e1 = valid ? __expf(acc[tile][1]) : 0.f;
        float e2 = valid ? __expf(acc[tile][2]) : 0.f;
        float e3 = valid ? __expf(acc[tile][3]) : 0.f;
        if (valid) {
            *(float2*)&g_logits[(size_t)row0 * CC + cc] = make_float2(e0, e1);
            *(float2*)&g_logits[(size_t)row1 * CC + cc] = make_float2(e2, e3);
        }
        s0 += e0 + e1;
        s1 += e2 + e3;
    }
    s0 += __shfl_xor_sync(0xffffffffu, s0, 1);
    s0 += __shfl_xor_sync(0xffffffffu, s0, 2);
    s1 += __shfl_xor_sync(0xffffffffu, s1, 1);
    s1 += __shfl_xor_sync(0xffffffffu, s1, 2);
    if (t == 0) {
        rpart[wn * 66 + row0] = s0;
        rpart[wn * 66 + row1] = s1;
    }
    __syncthreads();
    if (tid < BB) {
        g_psum[(size_t)tid * TILES5 + blockIdx.x] =
            rpart[tid] + rpart[66 + tid];
    }
}

// ---------------- kernel 6: scale exp by 1/rowsum ----------------
__global__ void k6_scale(float* __restrict__ out) {
    int b = blockIdx.x, ch = blockIdx.y, t = threadIdx.x;
    __shared__ float sred[8];
    float p = g_psum[(size_t)b * TILES5 + t];        // t < 256 < TILES5
    if (t + 256 < TILES5) p += g_psum[(size_t)b * TILES5 + t + 256];
#pragma unroll
    for (int off = 16; off; off >>= 1)
        p += __shfl_xor_sync(0xffffffffu, p, off);
    if ((t & 31) == 0) sred[t >> 5] = p;
    __syncthreads();
    float tot = ((sred[0] + sred[1]) + (sred[2] + sred[3])) +
                ((sred[4] + sred[5]) + (sred[6] + sred[7]));
    float inv = 1.0f / tot;

    int i = ch * 250 + t;
    if (t < 250) {
        float4 v = ((const float4*)(g_logits + (size_t)b * CC))[i];
        float4 r;
        r.x = v.x * inv; r.y = v.y * inv; r.z = v.z * inv; r.w = v.w * inv;
        ((float4*)(out + (size_t)b * CC))[i] = r;
    }
}

// ---------------- launch ----------------
extern "C" void kernel_launch(void* const* d_in, const int* in_sizes, int n_in,
                              void* d_out, int out_size) {
    const float* stories = (const float*)d_in[0];
    const float* queries = (const float*)d_in[1];
    const float* W1 = (const float*)d_in[2];
    const float* W2 = (const float*)d_in[3];
    const float* W3 = (const float*)d_in[4];
    const float* W4 = (const float*)d_in[5];
    float* out = (float*)d_out;

    static int k5_smem = 0;
    int smem5 = (8192 + 32 * WP5 + 2 * 66) * 4;  // ~50 KB -> 2 blocks/SM
    if (!k5_smem) {
        cudaFuncSetAttribute(k5_logits,
                             cudaFuncAttributeMaxDynamicSharedMemorySize, smem5);
        k5_smem = 1;
    }

    k1_reduce_stories<<<BB * MSPLIT + PREF, 256>>>(stories, queries, W1, W2, W3);
    dim3 g3(NSPLIT, 2, 2);
    k3_gemm64<<<g3, 256>>>(queries, W1, W2, W4);
    k4_hops<<<BB, EE>>>(W3);
    k5_logits<<<TILES5, 256, smem5>>>(W4);
    dim3 g6(BB, 10);
    k6_scale<<<g6, 256>>>(out);
}

// round 12
// speedup vs baseline: 1.1959x; 1.0034x over previous
#include <cuda_runtime.h>
#include <math.h>
#include <stdint.h>

#define BB 64
#define MM 512
#define SS 1024
#define EE 128
#define CC 10000
#define MSPLIT 8
#define NSPLIT 32
#define KCHUNK (SS / NSPLIT)  /* 32 */
#define PREF 8
#define TILES5 625            /* 10000/16 exact: 16-col tiles, one block each */

// ---------------- scratch (device globals; no allocation) ----------------
__device__ __align__(16) float g_partial[BB * MSPLIT * SS];   // 2 MB
__device__ __align__(16) float g_gpart[2 * NSPLIT * BB * EE]; // 2 MB
__device__ __align__(16) float g_uafrag[BB * EE];             // A fragments, mma order
__device__ __align__(16) float g_logits[BB * CC];             // 2.56 MB (exp(logits))
__device__ __align__(16) float g_psum[BB * TILES5];
__device__ __align__(16) float g_dummy[128 * 256];

// ---------------- kernel 1: reduce stories over M + prefetch weights ------------
__global__ void k1_reduce_stories(const float* __restrict__ stories,
                                  const float* __restrict__ queries,
                                  const float* __restrict__ W1,
                                  const float* __restrict__ W2,
                                  const float* __restrict__ W3) {
    int blk = blockIdx.x;
    int t = threadIdx.x;

    if (blk >= BB * MSPLIT) {  // ---- L2 prefetch blocks ----
        int lane = (blk - BB * MSPLIT) * 256 + t;
        float s = 0.f;
        const float4* a = (const float4*)W1;
        for (int i = lane; i < 32768; i += PREF * 256) {
            float4 v = __ldcg(&a[i]); s += v.x + v.y + v.z + v.w;
        }
        a = (const float4*)W2;
        for (int i = lane; i < 32768; i += PREF * 256) {
            float4 v = __ldcg(&a[i]); s += v.x + v.y + v.z + v.w;
        }
        a = (const float4*)queries;
        for (int i = lane; i < 16384; i += PREF * 256) {
            float4 v = __ldcg(&a[i]); s += v.x + v.y + v.z + v.w;
        }
        a = (const float4*)W3;
        for (int i = lane; i < 4096; i += PREF * 256) {
            float4 v = __ldcg(&a[i]); s += v.x + v.y + v.z + v.w;
        }
        g_dummy[lane] = s;
        return;
    }

    int b = blk / MSPLIT, ms = blk % MSPLIT;
    const float4* src =
        (const float4*)(stories + (size_t)(b * MM + ms * (MM / MSPLIT)) * SS);
    float4 a0 = make_float4(0.f, 0.f, 0.f, 0.f);
    float4 a1 = a0, a2 = a0, a3 = a0;
#pragma unroll 4
    for (int m = 0; m < MM / MSPLIT; m += 4) {
        float4 v0 = __ldcs(&src[(size_t)(m + 0) * (SS / 4) + t]);
        float4 v1 = __ldcs(&src[(size_t)(m + 1) * (SS / 4) + t]);
        float4 v2 = __ldcs(&src[(size_t)(m + 2) * (SS / 4) + t]);
        float4 v3 = __ldcs(&src[(size_t)(m + 3) * (SS / 4) + t]);
        a0.x += v0.x; a0.y += v0.y; a0.z += v0.z; a0.w += v0.w;
        a1.x += v1.x; a1.y += v1.y; a1.z += v1.z; a1.w += v1.w;
        a2.x += v2.x; a2.y += v2.y; a2.z += v2.z; a2.w += v2.w;
        a3.x += v3.x; a3.y += v3.y; a3.z += v3.z; a3.w += v3.w;
    }
    float4 r;
    r.x = (a0.x + a1.x) + (a2.x + a3.x);
    r.y = (a0.y + a1.y) + (a2.y + a3.y);
    r.z = (a0.z + a1.z) + (a2.z + a3.z);
    r.w = (a0.w + a1.w) + (a2.w + a3.w);
    ((float4*)g_partial)[(size_t)blk * (SS / 4) + t] = r;
}

// ---------------- kernel 3: u0 = queries@W1^T, o = ssum@W2^T (split-K x32) ------
__global__ void k3_gemm64(const float* __restrict__ queries,
                          const float* __restrict__ W1,
                          const float* __restrict__ W2,
                          const float* __restrict__ W4) {
    int ks = blockIdx.x;
    int eh = blockIdx.y;
    int which = blockIdx.z;
    const float* W = which ? W2 : W1;
    int kbase = ks * KCHUNK;

    // W4 L2 prefetch for k5 across 128 blocks
    int bid = ks + NSPLIT * eh + NSPLIT * 2 * which;  // 0..127
    int plane = bid * 256 + threadIdx.x;
    float ps = 0.f;
    const float4* w4 = (const float4*)W4;
    for (int i = plane; i < 320000; i += 128 * 256) {
        float4 v = __ldcg(&w4[i]); ps += v.x + v.y + v.z + v.w;
    }

    __shared__ __align__(16) float Xs[32][68];
    __shared__ __align__(16) float Ws[32][68];

    int tid = threadIdx.x;
    int tb = tid & 15, te = tid >> 4;
    int lrow = tid >> 3, lkq = tid & 7;

    float acc[16];
#pragma unroll
    for (int i = 0; i < 16; i++) acc[i] = 0.f;

    {
#pragma unroll
        for (int h = 0; h < 2; h++) {
            int row = lrow + 32 * h;
            float4 xv;
            if (which == 0) {
                xv = *(const float4*)&queries[(size_t)row * SS + kbase + lkq * 4];
            } else {
                xv = make_float4(0.f, 0.f, 0.f, 0.f);
#pragma unroll
                for (int msp = 0; msp < MSPLIT; msp++) {
                    float4 v = *(const float4*)&g_partial[
                        (size_t)(row * MSPLIT + msp) * SS + kbase + lkq * 4];
                    xv.x += v.x; xv.y += v.y; xv.z += v.z; xv.w += v.w;
                }
            }
            float4 wv = *(const float4*)&W[(size_t)(eh * 64 + row) * SS + kbase + lkq * 4];
            Xs[lkq * 4 + 0][row] = xv.x; Xs[lkq * 4 + 1][row] = xv.y;
            Xs[lkq * 4 + 2][row] = xv.z; Xs[lkq * 4 + 3][row] = xv.w;
            Ws[lkq * 4 + 0][row] = wv.x; Ws[lkq * 4 + 1][row] = wv.y;
            Ws[lkq * 4 + 2][row] = wv.z; Ws[lkq * 4 + 3][row] = wv.w;
        }
        __syncthreads();
#pragma unroll
        for (int k = 0; k < 32; k++) {
            float4 xv = *(const float4*)&Xs[k][tb * 4];
            float4 wv = *(const float4*)&Ws[k][te * 4];
            acc[0]  += xv.x * wv.x; acc[1]  += xv.x * wv.y;
            acc[2]  += xv.x * wv.z; acc[3]  += xv.x * wv.w;
            acc[4]  += xv.y * wv.x; acc[5]  += xv.y * wv.y;
            acc[6]  += xv.y * wv.z; acc[7]  += xv.y * wv.w;
            acc[8]  += xv.z * wv.x; acc[9]  += xv.z * wv.y;
            acc[10] += xv.z * wv.z; acc[11] += xv.z * wv.w;
            acc[12] += xv.w * wv.x; acc[13] += xv.w * wv.y;
            acc[14] += xv.w * wv.z; acc[15] += xv.w * wv.w;
        }
    }
#pragma unroll
    for (int i = 0; i < 4; i++)
#pragma unroll
        for (int j = 0; j < 4; j++)
            g_gpart[(size_t)((which * NSPLIT + ks) * BB + tb * 4 + i) * EE +
                    eh * 64 + te * 4 + j] = acc[i * 4 + j];
    g_dummy[plane] = ps;
}

// ---------------- kernel 4: split-K combine + hops + norm; writes A-frags -------
// Final u written as tf32-rounded mma A-fragments (m16n8k8 layout):
// a0=(g,t) a1=(g+8,t) a2=(g,t+4) a3=(g+8,t+4), lane = g*4+t.
__global__ void k4_hops(const float* __restrict__ W3) {
    __shared__ float us[EE];
    __shared__ float red[4];
    int b = blockIdx.x;
    int f = threadIdx.x;

    float4 w[32];
    const float4* wrow = (const float4*)(W3 + (size_t)f * EE);
#pragma unroll
    for (int q = 0; q < 32; q++) w[q] = __ldcg(&wrow[q]);

    float u = 0.f, o = 0.f;
#pragma unroll
    for (int ks = 0; ks < NSPLIT; ks++) {
        u += g_gpart[(size_t)(ks * BB + b) * EE + f];
        o += g_gpart[(size_t)((NSPLIT + ks) * BB + b) * EE + f];
    }
    us[f] = u;
    __syncthreads();

    float vout = 0.f;
    const float4* us4 = (const float4*)us;
    for (int hop = 0; hop < 3; hop++) {
        float v0 = 0.f, v1 = 0.f, v2 = 0.f, v3 = 0.f;
#pragma unroll
        for (int q = 0; q < 32; q++) {
            float4 uu = us4[q];
            v0 += w[q].x * uu.x;
            v1 += w[q].y * uu.y;
            v2 += w[q].z * uu.z;
            v3 += w[q].w * uu.w;
        }
        float v = o + ((v0 + v1) + (v2 + v3));
        float s = v * v;
#pragma unroll
        for (int off = 16; off; off >>= 1)
            s += __shfl_xor_sync(0xffffffffu, s, off);
        if ((f & 31) == 0) red[f >> 5] = s;
        __syncthreads();
        float tot = (red[0] + red[1]) + (red[2] + red[3]);
        float nrm = fmaxf(sqrtf(tot), 1e-12f);
        vout = v / nrm;
        us[f] = vout;
        __syncthreads();
    }

    // scatter into mma A-fragment order, tf32-rounded
    int wm = b >> 4, r = b & 15, rh = r >> 3, g = r & 7;
    int kstep = f >> 3, kt = f & 7, ch = kt >> 2, t = kt & 3;
    uint32_t bits;
    asm("cvt.rna.tf32.f32 %0, %1;" : "=r"(bits) : "f"(vout));
    g_uafrag[(size_t)(((wm * 16 + kstep) * 32 + (g * 4 + t)) * 4) + (ch * 2 + rh)] =
        __uint_as_float(bits);
}

// ---------------- kernel 5: exp(u @ W4^T) via tf32 mma, 4+ blocks/SM ------------
// grid = 625 (64b x 16c tile, K=128 = 16 mma steps; 10000 = 625*16 exact, no
// bounds checks), block = 256 (8 warps = 4 m-strips x 2 n8-halves; warp tile
// m16 x n8 = 1 mma per k-step). smem ~42 KB; residency 4.22 blocks/SM.
#define WP5 132
__global__ void __launch_bounds__(256) k5_logits(const float* __restrict__ W4) {
    extern __shared__ float sm5[];
    float* As = sm5;                       // 8192 floats: A fragments
    float* Ws = sm5 + 8192;                // 16 x 132
    float* rpart = sm5 + 8192 + 16 * WP5;  // 2 x 66

    int tid = threadIdx.x;
    int c0 = blockIdx.x * 16;

    // ---- stage A fragments (straight copy, 32 KB) ----
    {
        const float4* af = (const float4*)g_uafrag;
        float4* ad = (float4*)As;
#pragma unroll
        for (int i = 0; i < 8; i++) ad[tid + 256 * i] = af[tid + 256 * i];
    }
    // ---- stage W4 tile [c][k] with tf32 rounding (16 cols) ----
    {
        int c = tid >> 4, h = tid & 15;    // col 0..15, k-16th 0..15
        const float4* wsrc = (const float4*)(W4 + (size_t)(c0 + c) * EE);
#pragma unroll
        for (int i = 0; i < 2; i++) {
            int q = h * 2 + i;             // k-quad 0..31
            float4 wv = wsrc[q];
            uint32_t q0, q1, q2, q3;
            asm("cvt.rna.tf32.f32 %0, %1;" : "=r"(q0) : "f"(wv.x));
            asm("cvt.rna.tf32.f32 %0, %1;" : "=r"(q1) : "f"(wv.y));
            asm("cvt.rna.tf32.f32 %0, %1;" : "=r"(q2) : "f"(wv.z));
            asm("cvt.rna.tf32.f32 %0, %1;" : "=r"(q3) : "f"(wv.w));
            *(float4*)&Ws[c * WP5 + q * 4] =
                make_float4(__uint_as_float(q0), __uint_as_float(q1),
                            __uint_as_float(q2), __uint_as_float(q3));
        }
    }
    __syncthreads();

    int w = tid >> 5, l = tid & 31;
    int wm = w & 3, wn = w >> 2;           // 4 m-strips x 2 n8-halves
    int g = l >> 2, t = l & 3;

    float acc[4];
    acc[0] = acc[1] = acc[2] = acc[3] = 0.f;

#pragma unroll
    for (int ks = 0; ks < 16; ks++) {
        float4 av = ((const float4*)As)[(wm * 16 + ks) * 32 + l];
        uint32_t a0 = __float_as_uint(av.x), a1 = __float_as_uint(av.y);
        uint32_t a2 = __float_as_uint(av.z), a3 = __float_as_uint(av.w);
        int cc = wn * 8 + g;
        uint32_t b0 = __float_as_uint(Ws[cc * WP5 + ks * 8 + t]);
        uint32_t b1 = __float_as_uint(Ws[cc * WP5 + ks * 8 + t + 4]);
        asm volatile(
            "mma.sync.aligned.m16n8k8.row.col.f32.tf32.tf32.f32 "
            "{%0,%1,%2,%3}, {%4,%5,%6,%7}, {%8,%9}, {%0,%1,%2,%3};"
            : "+f"(acc[0]), "+f"(acc[1]), "+f"(acc[2]), "+f"(acc[3])
            : "r"(a0), "r"(a1), "r"(a2), "r"(a3), "r"(b0), "r"(b1));
    }

    // ---- epilogue: exp, float2 stores, row partial sums ----
    int row0 = wm * 16 + g, row1 = row0 + 8;
    int cc = c0 + wn * 8 + 2 * t;
    float e0 = __expf(acc[0]);
    float e1 = __expf(acc[1]);
    float e2 = __expf(acc[2]);
    float e3 = __expf(acc[3]);
    *(float2*)&g_logits[(size_t)row0 * CC + cc] = make_float2(e0, e1);
    *(float2*)&g_logits[(size_t)row1 * CC + cc] = make_float2(e2, e3);
    float s0 = e0 + e1;
    float s1 = e2 + e3;
    s0 += __shfl_xor_sync(0xffffffffu, s0, 1);
    s0 += __shfl_xor_sync(0xffffffffu, s0, 2);
    s1 += __shfl_xor_sync(0xffffffffu, s1, 1);
    s1 += __shfl_xor_sync(0xffffffffu, s1, 2);
    if (t == 0) {
        rpart[wn * 66 + row0] = s0;
        rpart[wn * 66 + row1] = s1;
    }
    __syncthreads();
    if (tid < BB) {
        g_psum[(size_t)tid * TILES5 + blockIdx.x] =
            rpart[tid] + rpart[66 + tid];
    }
}

// ---------------- kernel 6: scale exp by 1/rowsum ----------------
__global__ void k6_scale(float* __restrict__ out) {
    int b = blockIdx.x, ch = blockIdx.y, t = threadIdx.x;
    __shared__ float sred[8];
    const float* prow = g_psum + (size_t)b * TILES5;
    float p = prow[t] + prow[t + 256];              // 0..511
    if (t < TILES5 - 512) p += prow[t + 512];       // 512..624
#pragma unroll
    for (int off = 16; off; off >>= 1)
        p += __shfl_xor_sync(0xffffffffu, p, off);
    if ((t & 31) == 0) sred[t >> 5] = p;
    __syncthreads();
    float tot = ((sred[0] + sred[1]) + (sred[2] + sred[3])) +
                ((sred[4] + sred[5]) + (sred[6] + sred[7]));
    float inv = 1.0f / tot;

    int i = ch * 250 + t;
    if (t < 250) {
        float4 v = ((const float4*)(g_logits + (size_t)b * CC))[i];
        float4 r;
        r.x = v.x * inv; r.y = v.y * inv; r.z = v.z * inv; r.w = v.w * inv;
        ((float4*)(out + (size_t)b * CC))[i] = r;
    }
}

// ---------------- launch ----------------
extern "C" void kernel_launch(void* const* d_in, const int* in_sizes, int n_in,
                              void* d_out, int out_size) {
    const float* stories = (const float*)d_in[0];
    const float* queries = (const float*)d_in[1];
    const float* W1 = (const float*)d_in[2];
    const float* W2 = (const float*)d_in[3];
    const float* W3 = (const float*)d_in[4];
    const float* W4 = (const float*)d_in[5];
    float* out = (float*)d_out;

    static int k5_smem = 0;
    int smem5 = (8192 + 16 * WP5 + 2 * 66) * 4;  // ~42 KB -> 4+ blocks/SM
    if (!k5_smem) {
        cudaFuncSetAttribute(k5_logits,
                             cudaFuncAttributeMaxDynamicSharedMemorySize, smem5);
        k5_smem = 1;
    }

    k1_reduce_stories<<<BB * MSPLIT + PREF, 256>>>(stories, queries, W1, W2, W3);
    dim3 g3(NSPLIT, 2, 2);
    k3_gemm64<<<g3, 256>>>(queries, W1, W2, W4);
    k4_hops<<<BB, EE>>>(W3);
    k5_logits<<<TILES5, 256, smem5>>>(W4);
    dim3 g6(BB, 10);
    k6_scale<<<g6, 256>>>(out);
}

// round 13
// speedup vs baseline: 1.2235x; 1.0230x over previous
#include <cuda_runtime.h>
#include <math.h>
#include <stdint.h>

#define BB 64
#define MM 512
#define SS 1024
#define EE 128
#define CC 10000
#define MSPLIT 8
#define NSPLIT 32
#define KCHUNK (SS / NSPLIT)  /* 32 */
#define PREF 8
#define TILES5 625            /* 10000/16 exact: 16-col tiles, one block each */

// ---------------- scratch (device globals; no allocation) ----------------
__device__ __align__(16) float g_partial[BB * MSPLIT * SS];   // 2 MB
__device__ __align__(16) float g_gpart[2 * NSPLIT * BB * EE]; // 2 MB
__device__ __align__(16) float g_uafrag[BB * EE];             // A fragments, mma order
__device__ __align__(16) float g_logits[BB * CC];             // 2.56 MB (exp(logits))
__device__ __align__(16) float g_psum[BB * TILES5];
__device__ __align__(16) float g_dummy[128 * 256];

// ---------------- kernel 1: reduce stories over M + prefetch weights ------------
__global__ void k1_reduce_stories(const float* __restrict__ stories,
                                  const float* __restrict__ queries,
                                  const float* __restrict__ W1,
                                  const float* __restrict__ W2,
                                  const float* __restrict__ W3) {
    int blk = blockIdx.x;
    int t = threadIdx.x;

    if (blk >= BB * MSPLIT) {  // ---- L2 prefetch blocks ----
        int lane = (blk - BB * MSPLIT) * 256 + t;
        float s = 0.f;
        const float4* a = (const float4*)W1;
        for (int i = lane; i < 32768; i += PREF * 256) {
            float4 v = __ldcg(&a[i]); s += v.x + v.y + v.z + v.w;
        }
        a = (const float4*)W2;
        for (int i = lane; i < 32768; i += PREF * 256) {
            float4 v = __ldcg(&a[i]); s += v.x + v.y + v.z + v.w;
        }
        a = (const float4*)queries;
        for (int i = lane; i < 16384; i += PREF * 256) {
            float4 v = __ldcg(&a[i]); s += v.x + v.y + v.z + v.w;
        }
        a = (const float4*)W3;
        for (int i = lane; i < 4096; i += PREF * 256) {
            float4 v = __ldcg(&a[i]); s += v.x + v.y + v.z + v.w;
        }
        g_dummy[lane] = s;
        return;
    }

    int b = blk / MSPLIT, ms = blk % MSPLIT;
    const float4* src =
        (const float4*)(stories + (size_t)(b * MM + ms * (MM / MSPLIT)) * SS);
    float4 a0 = make_float4(0.f, 0.f, 0.f, 0.f);
    float4 a1 = a0, a2 = a0, a3 = a0;
#pragma unroll 4
    for (int m = 0; m < MM / MSPLIT; m += 4) {
        float4 v0 = __ldcs(&src[(size_t)(m + 0) * (SS / 4) + t]);
        float4 v1 = __ldcs(&src[(size_t)(m + 1) * (SS / 4) + t]);
        float4 v2 = __ldcs(&src[(size_t)(m + 2) * (SS / 4) + t]);
        float4 v3 = __ldcs(&src[(size_t)(m + 3) * (SS / 4) + t]);
        a0.x += v0.x; a0.y += v0.y; a0.z += v0.z; a0.w += v0.w;
        a1.x += v1.x; a1.y += v1.y; a1.z += v1.z; a1.w += v1.w;
        a2.x += v2.x; a2.y += v2.y; a2.z += v2.z; a2.w += v2.w;
        a3.x += v3.x; a3.y += v3.y; a3.z += v3.z; a3.w += v3.w;
    }
    float4 r;
    r.x = (a0.x + a1.x) + (a2.x + a3.x);
    r.y = (a0.y + a1.y) + (a2.y + a3.y);
    r.z = (a0.z + a1.z) + (a2.z + a3.z);
    r.w = (a0.w + a1.w) + (a2.w + a3.w);
    ((float4*)g_partial)[(size_t)blk * (SS / 4) + t] = r;
}

// ---------------- kernel 3: u0 = queries@W1^T, o = ssum@W2^T (split-K x32) ------
__global__ void k3_gemm64(const float* __restrict__ queries,
                          const float* __restrict__ W1,
                          const float* __restrict__ W2,
                          const float* __restrict__ W4) {
    int ks = blockIdx.x;
    int eh = blockIdx.y;
    int which = blockIdx.z;
    const float* W = which ? W2 : W1;
    int kbase = ks * KCHUNK;

    // W4 L2 prefetch for k5 across 128 blocks
    int bid = ks + NSPLIT * eh + NSPLIT * 2 * which;  // 0..127
    int plane = bid * 256 + threadIdx.x;
    float ps = 0.f;
    const float4* w4 = (const float4*)W4;
    for (int i = plane; i < 320000; i += 128 * 256) {
        float4 v = __ldcg(&w4[i]); ps += v.x + v.y + v.z + v.w;
    }

    __shared__ __align__(16) float Xs[32][68];
    __shared__ __align__(16) float Ws[32][68];

    int tid = threadIdx.x;
    int tb = tid & 15, te = tid >> 4;
    int lrow = tid >> 3, lkq = tid & 7;

    float acc[16];
#pragma unroll
    for (int i = 0; i < 16; i++) acc[i] = 0.f;

    {
#pragma unroll
        for (int h = 0; h < 2; h++) {
            int row = lrow + 32 * h;
            float4 xv;
            if (which == 0) {
                xv = *(const float4*)&queries[(size_t)row * SS + kbase + lkq * 4];
            } else {
                xv = make_float4(0.f, 0.f, 0.f, 0.f);
#pragma unroll
                for (int msp = 0; msp < MSPLIT; msp++) {
                    float4 v = *(const float4*)&g_partial[
                        (size_t)(row * MSPLIT + msp) * SS + kbase + lkq * 4];
                    xv.x += v.x; xv.y += v.y; xv.z += v.z; xv.w += v.w;
                }
            }
            float4 wv = *(const float4*)&W[(size_t)(eh * 64 + row) * SS + kbase + lkq * 4];
            Xs[lkq * 4 + 0][row] = xv.x; Xs[lkq * 4 + 1][row] = xv.y;
            Xs[lkq * 4 + 2][row] = xv.z; Xs[lkq * 4 + 3][row] = xv.w;
            Ws[lkq * 4 + 0][row] = wv.x; Ws[lkq * 4 + 1][row] = wv.y;
            Ws[lkq * 4 + 2][row] = wv.z; Ws[lkq * 4 + 3][row] = wv.w;
        }
        __syncthreads();
#pragma unroll
        for (int k = 0; k < 32; k++) {
            float4 xv = *(const float4*)&Xs[k][tb * 4];
            float4 wv = *(const float4*)&Ws[k][te * 4];
            acc[0]  += xv.x * wv.x; acc[1]  += xv.x * wv.y;
            acc[2]  += xv.x * wv.z; acc[3]  += xv.x * wv.w;
            acc[4]  += xv.y * wv.x; acc[5]  += xv.y * wv.y;
            acc[6]  += xv.y * wv.z; acc[7]  += xv.y * wv.w;
            acc[8]  += xv.z * wv.x; acc[9]  += xv.z * wv.y;
            acc[10] += xv.z * wv.z; acc[11] += xv.z * wv.w;
            acc[12] += xv.w * wv.x; acc[13] += xv.w * wv.y;
            acc[14] += xv.w * wv.z; acc[15] += xv.w * wv.w;
        }
    }
#pragma unroll
    for (int i = 0; i < 4; i++)
#pragma unroll
        for (int j = 0; j < 4; j++)
            g_gpart[(size_t)((which * NSPLIT + ks) * BB + tb * 4 + i) * EE +
                    eh * 64 + te * 4 + j] = acc[i * 4 + j];
    g_dummy[plane] = ps;
}

// ---------------- kernel 4: split-K combine + hops + norm; writes A-frags -------
// Final u written as tf32-rounded mma A-fragments (m16n8k8 layout):
// a0=(g,t) a1=(g+8,t) a2=(g,t+4) a3=(g+8,t+4), lane = g*4+t.
__global__ void k4_hops(const float* __restrict__ W3) {
    __shared__ float us[EE];
    __shared__ float red[4];
    int b = blockIdx.x;
    int f = threadIdx.x;

    float4 w[32];
    const float4* wrow = (const float4*)(W3 + (size_t)f * EE);
#pragma unroll
    for (int q = 0; q < 32; q++) w[q] = __ldcg(&wrow[q]);

    float u = 0.f, o = 0.f;
#pragma unroll
    for (int ks = 0; ks < NSPLIT; ks++) {
        u += g_gpart[(size_t)(ks * BB + b) * EE + f];
        o += g_gpart[(size_t)((NSPLIT + ks) * BB + b) * EE + f];
    }
    us[f] = u;
    __syncthreads();

    float vout = 0.f;
    const float4* us4 = (const float4*)us;
    for (int hop = 0; hop < 3; hop++) {
        float v0 = 0.f, v1 = 0.f, v2 = 0.f, v3 = 0.f;
#pragma unroll
        for (int q = 0; q < 32; q++) {
            float4 uu = us4[q];
            v0 += w[q].x * uu.x;
            v1 += w[q].y * uu.y;
            v2 += w[q].z * uu.z;
            v3 += w[q].w * uu.w;
        }
        float v = o + ((v0 + v1) + (v2 + v3));
        float s = v * v;
#pragma unroll
        for (int off = 16; off; off >>= 1)
            s += __shfl_xor_sync(0xffffffffu, s, off);
        if ((f & 31) == 0) red[f >> 5] = s;
        __syncthreads();
        float tot = (red[0] + red[1]) + (red[2] + red[3]);
        float nrm = fmaxf(sqrtf(tot), 1e-12f);
        vout = v / nrm;
        us[f] = vout;
        __syncthreads();
    }

    // scatter into mma A-fragment order, tf32-rounded
    int wm = b >> 4, r = b & 15, rh = r >> 3, g = r & 7;
    int kstep = f >> 3, kt = f & 7, ch = kt >> 2, t = kt & 3;
    uint32_t bits;
    asm("cvt.rna.tf32.f32 %0, %1;" : "=r"(bits) : "f"(vout));
    g_uafrag[(size_t)(((wm * 16 + kstep) * 32 + (g * 4 + t)) * 4) + (ch * 2 + rh)] =
        __uint_as_float(bits);
}

// ---------------- kernel 5: exp(u @ W4^T) via tf32 mma, A direct from L1/L2 -----
// grid = 625 (64b x 16c tile, K=128 = 16 mma steps), block = 256 (8 warps =
// 4 m-strips x 2 n8-halves). A fragments are IDENTICAL for every block and
// L1/L2-resident -> read directly with __ldg in the mainloop (no smem staging,
// no barrier on A). Only the 16-col W tile (tf32 cvt + cross-warp share) uses
// shared memory (~8.6 KB static -> high residency, tiny prologue).
#define WP5 132
__global__ void __launch_bounds__(256) k5_logits(const float* __restrict__ W4) {
    __shared__ __align__(16) float Ws[16 * WP5];
    __shared__ float rpart[2 * 66];

    int tid = threadIdx.x;
    int c0 = blockIdx.x * 16;

    // ---- stage W4 tile [c][k] with tf32 rounding (16 cols, 2 float4/thread) ----
    {
        int c = tid >> 4, h = tid & 15;    // col 0..15, k-16th 0..15
        const float4* wsrc = (const float4*)(W4 + (size_t)(c0 + c) * EE);
#pragma unroll
        for (int i = 0; i < 2; i++) {
            int q = h * 2 + i;             // k-quad 0..31
            float4 wv = wsrc[q];
            uint32_t q0, q1, q2, q3;
            asm("cvt.rna.tf32.f32 %0, %1;" : "=r"(q0) : "f"(wv.x));
            asm("cvt.rna.tf32.f32 %0, %1;" : "=r"(q1) : "f"(wv.y));
            asm("cvt.rna.tf32.f32 %0, %1;" : "=r"(q2) : "f"(wv.z));
            asm("cvt.rna.tf32.f32 %0, %1;" : "=r"(q3) : "f"(wv.w));
            *(float4*)&Ws[c * WP5 + q * 4] =
                make_float4(__uint_as_float(q0), __uint_as_float(q1),
                            __uint_as_float(q2), __uint_as_float(q3));
        }
    }
    __syncthreads();

    int w = tid >> 5, l = tid & 31;
    int wm = w & 3, wn = w >> 2;           // 4 m-strips x 2 n8-halves
    int g = l >> 2, t = l & 3;

    const float4* afr = (const float4*)g_uafrag;

    float acc[4];
    acc[0] = acc[1] = acc[2] = acc[3] = 0.f;

#pragma unroll
    for (int ks = 0; ks < 16; ks++) {
        float4 av = __ldg(&afr[(wm * 16 + ks) * 32 + l]);
        uint32_t a0 = __float_as_uint(av.x), a1 = __float_as_uint(av.y);
        uint32_t a2 = __float_as_uint(av.z), a3 = __float_as_uint(av.w);
        int cc = wn * 8 + g;
        uint32_t b0 = __float_as_uint(Ws[cc * WP5 + ks * 8 + t]);
        uint32_t b1 = __float_as_uint(Ws[cc * WP5 + ks * 8 + t + 4]);
        asm volatile(
            "mma.sync.aligned.m16n8k8.row.col.f32.tf32.tf32.f32 "
            "{%0,%1,%2,%3}, {%4,%5,%6,%7}, {%8,%9}, {%0,%1,%2,%3};"
            : "+f"(acc[0]), "+f"(acc[1]), "+f"(acc[2]), "+f"(acc[3])
            : "r"(a0), "r"(a1), "r"(a2), "r"(a3), "r"(b0), "r"(b1));
    }

    // ---- epilogue: exp, float2 stores, row partial sums ----
    int row0 = wm * 16 + g, row1 = row0 + 8;
    int cc = c0 + wn * 8 + 2 * t;
    float e0 = __expf(acc[0]);
    float e1 = __expf(acc[1]);
    float e2 = __expf(acc[2]);
    float e3 = __expf(acc[3]);
    *(float2*)&g_logits[(size_t)row0 * CC + cc] = make_float2(e0, e1);
    *(float2*)&g_logits[(size_t)row1 * CC + cc] = make_float2(e2, e3);
    float s0 = e0 + e1;
    float s1 = e2 + e3;
    s0 += __shfl_xor_sync(0xffffffffu, s0, 1);
    s0 += __shfl_xor_sync(0xffffffffu, s0, 2);
    s1 += __shfl_xor_sync(0xffffffffu, s1, 1);
    s1 += __shfl_xor_sync(0xffffffffu, s1, 2);
    if (t == 0) {
        rpart[wn * 66 + row0] = s0;
        rpart[wn * 66 + row1] = s1;
    }
    __syncthreads();
    if (tid < BB) {
        g_psum[(size_t)tid * TILES5 + blockIdx.x] =
            rpart[tid] + rpart[66 + tid];
    }
}

// ---------------- kernel 6: scale exp by 1/rowsum ----------------
__global__ void k6_scale(float* __restrict__ out) {
    int b = blockIdx.x, ch = blockIdx.y, t = threadIdx.x;
    __shared__ float sred[8];
    const float* prow = g_psum + (size_t)b * TILES5;
    float p = prow[t] + prow[t + 256];              // 0..511
    if (t < TILES5 - 512) p += prow[t + 512];       // 512..624
#pragma unroll
    for (int off = 16; off; off >>= 1)
        p += __shfl_xor_sync(0xffffffffu, p, off);
    if ((t & 31) == 0) sred[t >> 5] = p;
    __syncthreads();
    float tot = ((sred[0] + sred[1]) + (sred[2] + sred[3])) +
                ((sred[4] + sred[5]) + (sred[6] + sred[7]));
    float inv = 1.0f / tot;

    int i = ch * 250 + t;
    if (t < 250) {
        float4 v = ((const float4*)(g_logits + (size_t)b * CC))[i];
        float4 r;
        r.x = v.x * inv; r.y = v.y * inv; r.z = v.z * inv; r.w = v.w * inv;
        ((float4*)(out + (size_t)b * CC))[i] = r;
    }
}

// ---------------- launch ----------------
extern "C" void kernel_launch(void* const* d_in, const int* in_sizes, int n_in,
                              void* d_out, int out_size) {
    const float* stories = (const float*)d_in[0];
    const float* queries = (const float*)d_in[1];
    const float* W1 = (const float*)d_in[2];
    const float* W2 = (const float*)d_in[3];
    const float* W3 = (const float*)d_in[4];
    const float* W4 = (const float*)d_in[5];
    float* out = (float*)d_out;

    k1_reduce_stories<<<BB * MSPLIT + PREF, 256>>>(stories, queries, W1, W2, W3);
    dim3 g3(NSPLIT, 2, 2);
    k3_gemm64<<<g3, 256>>>(queries, W1, W2, W4);
    k4_hops<<<BB, EE>>>(W3);
    k5_logits<<<TILES5, 256>>>(W4);
    dim3 g6(BB, 10);
    k6_scale<<<g6, 256>>>(out);
}

// round 14
// speedup vs baseline: 1.2303x; 1.0056x over previous
#include <cuda_runtime.h>
#include <math.h>
#include <stdint.h>

#define BB 64
#define MM 512
#define SS 1024
#define EE 128
#define CC 10000
#define MSPLIT 8
#define NSPLIT 32
#define KCHUNK (SS / NSPLIT)  /* 32 */
#define PREF 16
#define TILES5 625            /* 10000/16 exact: 16-col tiles, one block each */

// ---------------- scratch (device globals; no allocation) ----------------
__device__ __align__(16) float g_partial[BB * MSPLIT * SS];   // 2 MB
__device__ __align__(16) float g_gpart[2 * NSPLIT * BB * EE]; // 2 MB
__device__ __align__(16) float g_uafrag[BB * EE];             // A fragments, mma order
__device__ __align__(16) float g_logits[BB * CC];             // 2.56 MB (exp(logits))
__device__ __align__(16) float g_psum[BB * TILES5];
__device__ __align__(16) float g_dummy[PREF * 256];

// ---------------- kernel 1: reduce stories over M + prefetch ALL weights --------
// blocks [0, BB*MSPLIT): sum 64 m-rows over S, MLP=8 streaming loads.
// blocks [BB*MSPLIT, +PREF): pull W1/W2/queries/W3/W4 into L2 under k1's shadow.
__global__ void k1_reduce_stories(const float* __restrict__ stories,
                                  const float* __restrict__ queries,
                                  const float* __restrict__ W1,
                                  const float* __restrict__ W2,
                                  const float* __restrict__ W3,
                                  const float* __restrict__ W4) {
    int blk = blockIdx.x;
    int t = threadIdx.x;

    if (blk >= BB * MSPLIT) {  // ---- L2 prefetch blocks ----
        int lane = (blk - BB * MSPLIT) * 256 + t;  // 0..4095
        float s = 0.f;
        const float4* a = (const float4*)W1;       // 32768 float4
        for (int i = lane; i < 32768; i += PREF * 256) {
            float4 v = __ldcg(&a[i]); s += v.x + v.y + v.z + v.w;
        }
        a = (const float4*)W2;
        for (int i = lane; i < 32768; i += PREF * 256) {
            float4 v = __ldcg(&a[i]); s += v.x + v.y + v.z + v.w;
        }
        a = (const float4*)queries;                // 16384 float4
        for (int i = lane; i < 16384; i += PREF * 256) {
            float4 v = __ldcg(&a[i]); s += v.x + v.y + v.z + v.w;
        }
        a = (const float4*)W3;                     // 4096 float4
        for (int i = lane; i < 4096; i += PREF * 256) {
            float4 v = __ldcg(&a[i]); s += v.x + v.y + v.z + v.w;
        }
        a = (const float4*)W4;                     // 320000 float4
        for (int i = lane; i < 320000; i += PREF * 256) {
            float4 v = __ldcg(&a[i]); s += v.x + v.y + v.z + v.w;
        }
        g_dummy[lane] = s;
        return;
    }

    int b = blk / MSPLIT, ms = blk % MSPLIT;
    const float4* src =
        (const float4*)(stories + (size_t)(b * MM + ms * (MM / MSPLIT)) * SS);
    float4 a0 = make_float4(0.f, 0.f, 0.f, 0.f);
    float4 a1 = a0, a2 = a0, a3 = a0, a4 = a0, a5 = a0, a6 = a0, a7 = a0;
#pragma unroll
    for (int m = 0; m < MM / MSPLIT; m += 8) {
        float4 v0 = __ldcs(&src[(size_t)(m + 0) * (SS / 4) + t]);
        float4 v1 = __ldcs(&src[(size_t)(m + 1) * (SS / 4) + t]);
        float4 v2 = __ldcs(&src[(size_t)(m + 2) * (SS / 4) + t]);
        float4 v3 = __ldcs(&src[(size_t)(m + 3) * (SS / 4) + t]);
        float4 v4 = __ldcs(&src[(size_t)(m + 4) * (SS / 4) + t]);
        float4 v5 = __ldcs(&src[(size_t)(m + 5) * (SS / 4) + t]);
        float4 v6 = __ldcs(&src[(size_t)(m + 6) * (SS / 4) + t]);
        float4 v7 = __ldcs(&src[(size_t)(m + 7) * (SS / 4) + t]);
        a0.x += v0.x; a0.y += v0.y; a0.z += v0.z; a0.w += v0.w;
        a1.x += v1.x; a1.y += v1.y; a1.z += v1.z; a1.w += v1.w;
        a2.x += v2.x; a2.y += v2.y; a2.z += v2.z; a2.w += v2.w;
        a3.x += v3.x; a3.y += v3.y; a3.z += v3.z; a3.w += v3.w;
        a4.x += v4.x; a4.y += v4.y; a4.z += v4.z; a4.w += v4.w;
        a5.x += v5.x; a5.y += v5.y; a5.z += v5.z; a5.w += v5.w;
        a6.x += v6.x; a6.y += v6.y; a6.z += v6.z; a6.w += v6.w;
        a7.x += v7.x; a7.y += v7.y; a7.z += v7.z; a7.w += v7.w;
    }
    float4 r;
    r.x = ((a0.x + a1.x) + (a2.x + a3.x)) + ((a4.x + a5.x) + (a6.x + a7.x));
    r.y = ((a0.y + a1.y) + (a2.y + a3.y)) + ((a4.y + a5.y) + (a6.y + a7.y));
    r.z = ((a0.z + a1.z) + (a2.z + a3.z)) + ((a4.z + a5.z) + (a6.z + a7.z));
    r.w = ((a0.w + a1.w) + (a2.w + a3.w)) + ((a4.w + a5.w) + (a6.w + a7.w));
    ((float4*)g_partial)[(size_t)blk * (SS / 4) + t] = r;
}

// ---------------- kernel 3: u0 = queries@W1^T, o = ssum@W2^T (split-K x32) ------
__global__ void k3_gemm64(const float* __restrict__ queries,
                          const float* __restrict__ W1,
                          const float* __restrict__ W2) {
    int ks = blockIdx.x;
    int eh = blockIdx.y;
    int which = blockIdx.z;
    const float* W = which ? W2 : W1;
    int kbase = ks * KCHUNK;

    __shared__ __align__(16) float Xs[32][68];
    __shared__ __align__(16) float Ws[32][68];

    int tid = threadIdx.x;
    int tb = tid & 15, te = tid >> 4;
    int lrow = tid >> 3, lkq = tid & 7;

    float acc[16];
#pragma unroll
    for (int i = 0; i < 16; i++) acc[i] = 0.f;

    {
#pragma unroll
        for (int h = 0; h < 2; h++) {
            int row = lrow + 32 * h;
            float4 xv;
            if (which == 0) {
                xv = *(const float4*)&queries[(size_t)row * SS + kbase + lkq * 4];
            } else {
                xv = make_float4(0.f, 0.f, 0.f, 0.f);
#pragma unroll
                for (int msp = 0; msp < MSPLIT; msp++) {
                    float4 v = *(const float4*)&g_partial[
                        (size_t)(row * MSPLIT + msp) * SS + kbase + lkq * 4];
                    xv.x += v.x; xv.y += v.y; xv.z += v.z; xv.w += v.w;
                }
            }
            float4 wv = *(const float4*)&W[(size_t)(eh * 64 + row) * SS + kbase + lkq * 4];
            Xs[lkq * 4 + 0][row] = xv.x; Xs[lkq * 4 + 1][row] = xv.y;
            Xs[lkq * 4 + 2][row] = xv.z; Xs[lkq * 4 + 3][row] = xv.w;
            Ws[lkq * 4 + 0][row] = wv.x; Ws[lkq * 4 + 1][row] = wv.y;
            Ws[lkq * 4 + 2][row] = wv.z; Ws[lkq * 4 + 3][row] = wv.w;
        }
        __syncthreads();
#pragma unroll
        for (int k = 0; k < 32; k++) {
            float4 xv = *(const float4*)&Xs[k][tb * 4];
            float4 wv = *(const float4*)&Ws[k][te * 4];
            acc[0]  += xv.x * wv.x; acc[1]  += xv.x * wv.y;
            acc[2]  += xv.x * wv.z; acc[3]  += xv.x * wv.w;
            acc[4]  += xv.y * wv.x; acc[5]  += xv.y * wv.y;
            acc[6]  += xv.y * wv.z; acc[7]  += xv.y * wv.w;
            acc[8]  += xv.z * wv.x; acc[9]  += xv.z * wv.y;
            acc[10] += xv.z * wv.z; acc[11] += xv.z * wv.w;
            acc[12] += xv.w * wv.x; acc[13] += xv.w * wv.y;
            acc[14] += xv.w * wv.z; acc[15] += xv.w * wv.w;
        }
    }
#pragma unroll
    for (int i = 0; i < 4; i++)
#pragma unroll
        for (int j = 0; j < 4; j++)
            g_gpart[(size_t)((which * NSPLIT + ks) * BB + tb * 4 + i) * EE +
                    eh * 64 + te * 4 + j] = acc[i * 4 + j];
}

// ---------------- kernel 4: split-K combine + hops + norm; writes A-frags -------
// Final u written as tf32-rounded mma A-fragments (m16n8k8 layout):
// a0=(g,t) a1=(g+8,t) a2=(g,t+4) a3=(g+8,t+4), lane = g*4+t.
__global__ void k4_hops(const float* __restrict__ W3) {
    __shared__ float us[EE];
    __shared__ float red[4];
    int b = blockIdx.x;
    int f = threadIdx.x;

    float4 w[32];
    const float4* wrow = (const float4*)(W3 + (size_t)f * EE);
#pragma unroll
    for (int q = 0; q < 32; q++) w[q] = __ldcg(&wrow[q]);

    float u = 0.f, o = 0.f;
#pragma unroll
    for (int ks = 0; ks < NSPLIT; ks++) {
        u += g_gpart[(size_t)(ks * BB + b) * EE + f];
        o += g_gpart[(size_t)((NSPLIT + ks) * BB + b) * EE + f];
    }
    us[f] = u;
    __syncthreads();

    float vout = 0.f;
    const float4* us4 = (const float4*)us;
    for (int hop = 0; hop < 3; hop++) {
        float v0 = 0.f, v1 = 0.f, v2 = 0.f, v3 = 0.f;
#pragma unroll
        for (int q = 0; q < 32; q++) {
            float4 uu = us4[q];
            v0 += w[q].x * uu.x;
            v1 += w[q].y * uu.y;
            v2 += w[q].z * uu.z;
            v3 += w[q].w * uu.w;
        }
        float v = o + ((v0 + v1) + (v2 + v3));
        float s = v * v;
#pragma unroll
        for (int off = 16; off; off >>= 1)
            s += __shfl_xor_sync(0xffffffffu, s, off);
        if ((f & 31) == 0) red[f >> 5] = s;
        __syncthreads();
        float tot = (red[0] + red[1]) + (red[2] + red[3]);
        float nrm = fmaxf(sqrtf(tot), 1e-12f);
        vout = v / nrm;
        us[f] = vout;
        __syncthreads();
    }

    // scatter into mma A-fragment order, tf32-rounded
    int wm = b >> 4, r = b & 15, rh = r >> 3, g = r & 7;
    int kstep = f >> 3, kt = f & 7, ch = kt >> 2, t = kt & 3;
    uint32_t bits;
    asm("cvt.rna.tf32.f32 %0, %1;" : "=r"(bits) : "f"(vout));
    g_uafrag[(size_t)(((wm * 16 + kstep) * 32 + (g * 4 + t)) * 4) + (ch * 2 + rh)] =
        __uint_as_float(bits);
}

// ---------------- kernel 5: exp(u @ W4^T) via tf32 mma, A direct from L1/L2 -----
// grid = 625 (64b x 16c tile, K=128 = 16 mma steps), block = 256 (8 warps =
// 4 m-strips x 2 n8-halves). A fragments identical per block -> __ldg direct.
// W tile in 8.6 KB static smem. W4 is L2-warm from k1's prefetch.
#define WP5 132
__global__ void __launch_bounds__(256) k5_logits(const float* __restrict__ W4) {
    __shared__ __align__(16) float Ws[16 * WP5];
    __shared__ float rpart[2 * 66];

    int tid = threadIdx.x;
    int c0 = blockIdx.x * 16;

    // ---- stage W4 tile [c][k] with tf32 rounding (16 cols, 2 float4/thread) ----
    {
        int c = tid >> 4, h = tid & 15;    // col 0..15, k-16th 0..15
        const float4* wsrc = (const float4*)(W4 + (size_t)(c0 + c) * EE);
#pragma unroll
        for (int i = 0; i < 2; i++) {
            int q = h * 2 + i;             // k-quad 0..31
            float4 wv = wsrc[q];
            uint32_t q0, q1, q2, q3;
            asm("cvt.rna.tf32.f32 %0, %1;" : "=r"(q0) : "f"(wv.x));
            asm("cvt.rna.tf32.f32 %0, %1;" : "=r"(q1) : "f"(wv.y));
            asm("cvt.rna.tf32.f32 %0, %1;" : "=r"(q2) : "f"(wv.z));
            asm("cvt.rna.tf32.f32 %0, %1;" : "=r"(q3) : "f"(wv.w));
            *(float4*)&Ws[c * WP5 + q * 4] =
                make_float4(__uint_as_float(q0), __uint_as_float(q1),
                            __uint_as_float(q2), __uint_as_float(q3));
        }
    }
    __syncthreads();

    int w = tid >> 5, l = tid & 31;
    int wm = w & 3, wn = w >> 2;           // 4 m-strips x 2 n8-halves
    int g = l >> 2, t = l & 3;

    const float4* afr = (const float4*)g_uafrag;

    float acc[4];
    acc[0] = acc[1] = acc[2] = acc[3] = 0.f;

#pragma unroll
    for (int ks = 0; ks < 16; ks++) {
        float4 av = __ldg(&afr[(wm * 16 + ks) * 32 + l]);
        uint32_t a0 = __float_as_uint(av.x), a1 = __float_as_uint(av.y);
        uint32_t a2 = __float_as_uint(av.z), a3 = __float_as_uint(av.w);
        int cc = wn * 8 + g;
        uint32_t b0 = __float_as_uint(Ws[cc * WP5 + ks * 8 + t]);
        uint32_t b1 = __float_as_uint(Ws[cc * WP5 + ks * 8 + t + 4]);
        asm volatile(
            "mma.sync.aligned.m16n8k8.row.col.f32.tf32.tf32.f32 "
            "{%0,%1,%2,%3}, {%4,%5,%6,%7}, {%8,%9}, {%0,%1,%2,%3};"
            : "+f"(acc[0]), "+f"(acc[1]), "+f"(acc[2]), "+f"(acc[3])
            : "r"(a0), "r"(a1), "r"(a2), "r"(a3), "r"(b0), "r"(b1));
    }

    // ---- epilogue: exp, float2 stores, row partial sums ----
    int row0 = wm * 16 + g, row1 = row0 + 8;
    int cc = c0 + wn * 8 + 2 * t;
    float e0 = __expf(acc[0]);
    float e1 = __expf(acc[1]);
    float e2 = __expf(acc[2]);
    float e3 = __expf(acc[3]);
    *(float2*)&g_logits[(size_t)row0 * CC + cc] = make_float2(e0, e1);
    *(float2*)&g_logits[(size_t)row1 * CC + cc] = make_float2(e2, e3);
    float s0 = e0 + e1;
    float s1 = e2 + e3;
    s0 += __shfl_xor_sync(0xffffffffu, s0, 1);
    s0 += __shfl_xor_sync(0xffffffffu, s0, 2);
    s1 += __shfl_xor_sync(0xffffffffu, s1, 1);
    s1 += __shfl_xor_sync(0xffffffffu, s1, 2);
    if (t == 0) {
        rpart[wn * 66 + row0] = s0;
        rpart[wn * 66 + row1] = s1;
    }
    __syncthreads();
    if (tid < BB) {
        g_psum[(size_t)tid * TILES5 + blockIdx.x] =
            rpart[tid] + rpart[66 + tid];
    }
}

// ---------------- kernel 6: scale exp by 1/rowsum ----------------
__global__ void k6_scale(float* __restrict__ out) {
    int b = blockIdx.x, ch = blockIdx.y, t = threadIdx.x;
    __shared__ float sred[8];
    const float* prow = g_psum + (size_t)b * TILES5;
    float p = prow[t] + prow[t + 256];              // 0..511
    if (t < TILES5 - 512) p += prow[t + 512];       // 512..624
#pragma unroll
    for (int off = 16; off; off >>= 1)
        p += __shfl_xor_sync(0xffffffffu, p, off);
    if ((t & 31) == 0) sred[t >> 5] = p;
    __syncthreads();
    float tot = ((sred[0] + sred[1]) + (sred[2] + sred[3])) +
                ((sred[4] + sred[5]) + (sred[6] + sred[7]));
    float inv = 1.0f / tot;

    int i = ch * 250 + t;
    if (t < 250) {
        float4 v = __ldcs(&((const float4*)(g_logits + (size_t)b * CC))[i]);
        float4 r;
        r.x = v.x * inv; r.y = v.y * inv; r.z = v.z * inv; r.w = v.w * inv;
        ((float4*)(out + (size_t)b * CC))[i] = r;
    }
}

// ---------------- launch ----------------
extern "C" void kernel_launch(void* const* d_in, const int* in_sizes, int n_in,
                              void* d_out, int out_size) {
    const float* stories = (const float*)d_in[0];
    const float* queries = (const float*)d_in[1];
    const float* W1 = (const float*)d_in[2];
    const float* W2 = (const float*)d_in[3];
    const float* W3 = (const float*)d_in[4];
    const float* W4 = (const float*)d_in[5];
    float* out = (float*)d_out;

    k1_reduce_stories<<<BB * MSPLIT + PREF, 256>>>(stories, queries, W1, W2, W3, W4);
    dim3 g3(NSPLIT, 2, 2);
    k3_gemm64<<<g3, 256>>>(queries, W1, W2);
    k4_hops<<<BB, EE>>>(W3);
    k5_logits<<<TILES5, 256>>>(W4);
    dim3 g6(BB, 10);
    k6_scale<<<g6, 256>>>(out);
}